// round 1
// baseline (speedup 1.0000x reference)
#include <cuda_runtime.h>
#include <math.h>

// Problem constants
#define B_  8
#define C_  512
#define MID_ 128
#define N_  2304           // H*W = 48*48
static const float EPS_ = 1e-5f;
static const float SCALE_ = 0.08838834764831845f;  // MID^-0.5

// ---------------- scratch (device globals; no cudaMalloc allowed) -------------
__device__ float g_fa [B_ * MID_ * N_];
__device__ float g_fv [B_ * MID_ * N_];
__device__ float g_fh [B_ * MID_ * N_];
__device__ float g_gav[B_ * MID_ * N_];
__device__ float g_gah[B_ * MID_ * N_];
__device__ float g_o  [B_ * MID_ * N_];
__device__ float g_S  [(long long)B_ * N_ * N_];   // 170 MB, reused for both attentions

// ---------------- generic tiled SGEMM ----------------------------------------
// C[m,n] = sum_k A(m,k) * B(k,n)   (per-batch via blockIdx.z and strides)
// TA=false: A row-major [M,K], element A[m*lda+k]
// TA=true : A stored [K,M],    element A[k*lda+m]   (for f^T f logits)
// B always row-major [K,N]: B[k*ldb+n].
// EPI: 0 = none, 1 = BN+ReLU (bias,gamma,beta), 2 = +bias, 3 = +bias +residual
// All dims are multiples of the tile sizes for this problem (no bounds checks).
template<bool TA, int EPI>
__global__ __launch_bounds__(256)
void gemm_k(const float* __restrict__ A, const float* __restrict__ Bp,
            float* __restrict__ C,
            int M, int N, int K, int lda, int ldb, int ldc,
            long long sA, long long sB, long long sC,
            const float* __restrict__ bias,
            const float* __restrict__ gamma,
            const float* __restrict__ beta,
            const float* __restrict__ res, long long sRes)
{
    constexpr int BM = 128, BN = 128, BK = 16;
    __shared__ __align__(16) float As[BK][BM + 4];
    __shared__ __align__(16) float Bs[BK][BN];

    const int bz = blockIdx.z;
    A  += (long long)bz * sA;
    Bp += (long long)bz * sB;
    C  += (long long)bz * sC;
    const float* R = (EPI == 3) ? (res + (long long)bz * sRes) : nullptr;

    const int bm = blockIdx.y * BM;
    const int bn = blockIdx.x * BN;
    const int tid = threadIdx.x;
    const int tx = tid & 15;        // 0..15 -> 8 cols each
    const int ty = tid >> 4;        // 0..15 -> 8 rows each

    float acc[8][8];
    #pragma unroll
    for (int i = 0; i < 8; ++i)
        #pragma unroll
        for (int j = 0; j < 8; ++j) acc[i][j] = 0.f;

    for (int k0 = 0; k0 < K; k0 += BK) {
        // ---- load A tile into As[k][m] ----
        if (TA) {
            const int kr = tid >> 4;          // 0..15
            const int mc = (tid & 15) * 4;    // 0..60
            #pragma unroll
            for (int h = 0; h < 2; ++h) {
                float4 v = *reinterpret_cast<const float4*>(
                    &A[(long long)(k0 + kr) * lda + bm + mc + h * 64]);
                *reinterpret_cast<float4*>(&As[kr][mc + h * 64]) = v;
            }
        } else {
            const int mr = tid >> 2;          // 0..63
            const int kc = (tid & 3) * 4;     // 0..12
            #pragma unroll
            for (int h = 0; h < 2; ++h) {
                float4 v = *reinterpret_cast<const float4*>(
                    &A[(long long)(bm + mr + h * 64) * lda + k0 + kc]);
                As[kc + 0][mr + h * 64] = v.x;
                As[kc + 1][mr + h * 64] = v.y;
                As[kc + 2][mr + h * 64] = v.z;
                As[kc + 3][mr + h * 64] = v.w;
            }
        }
        // ---- load B tile ----
        {
            const int kr = tid >> 4;
            const int nc = (tid & 15) * 4;
            #pragma unroll
            for (int h = 0; h < 2; ++h) {
                float4 v = *reinterpret_cast<const float4*>(
                    &Bp[(long long)(k0 + kr) * ldb + bn + nc + h * 64]);
                *reinterpret_cast<float4*>(&Bs[kr][nc + h * 64]) = v;
            }
        }
        __syncthreads();

        #pragma unroll
        for (int k = 0; k < BK; ++k) {
            float a[8], b[8];
            *reinterpret_cast<float4*>(&a[0]) = *reinterpret_cast<const float4*>(&As[k][ty * 8]);
            *reinterpret_cast<float4*>(&a[4]) = *reinterpret_cast<const float4*>(&As[k][ty * 8 + 4]);
            *reinterpret_cast<float4*>(&b[0]) = *reinterpret_cast<const float4*>(&Bs[k][tx * 8]);
            *reinterpret_cast<float4*>(&b[4]) = *reinterpret_cast<const float4*>(&Bs[k][tx * 8 + 4]);
            #pragma unroll
            for (int i = 0; i < 8; ++i)
                #pragma unroll
                for (int j = 0; j < 8; ++j)
                    acc[i][j] = fmaf(a[i], b[j], acc[i][j]);
        }
        __syncthreads();
    }

    // ---- epilogue ----
    #pragma unroll
    for (int i = 0; i < 8; ++i) {
        const int row = bm + ty * 8 + i;
        float bi = 0.f, sc = 1.f, sh = 0.f;
        if (EPI == 1) {
            bi = bias[row];
            sc = gamma[row] * rsqrtf(1.f + EPS_);
            sh = beta[row];
        } else if (EPI >= 2) {
            bi = bias[row];
        }
        const int col = bn + tx * 8;
        float out[8];
        #pragma unroll
        for (int j = 0; j < 8; ++j) {
            float v = acc[i][j];
            if (EPI == 1)      v = fmaxf(fmaf(v + bi, sc, sh), 0.f);
            else if (EPI == 2) v = v + bi;
            else if (EPI == 3) v = v + bi + R[(long long)row * ldc + col + j];
            out[j] = v;
        }
        *reinterpret_cast<float4*>(&C[(long long)row * ldc + col])     = *reinterpret_cast<float4*>(&out[0]);
        *reinterpret_cast<float4*>(&C[(long long)row * ldc + col + 4]) = *reinterpret_cast<float4*>(&out[4]);
    }
}

// ---------------- row softmax over scale*S, in place --------------------------
// one block per row; 2304 = 9 * 256
__global__ __launch_bounds__(256)
void softmax_k(float* __restrict__ S)
{
    const long long row = blockIdx.x;
    float* p = S + row * (long long)N_;
    const int tid = threadIdx.x;

    float v[9];
    float mx = -1e30f;
    #pragma unroll
    for (int i = 0; i < 9; ++i) {
        v[i] = p[tid + i * 256];
        mx = fmaxf(mx, v[i]);
    }

    __shared__ float red_max[8];
    __shared__ float red_sum[8];

    #pragma unroll
    for (int o = 16; o > 0; o >>= 1)
        mx = fmaxf(mx, __shfl_xor_sync(0xffffffffu, mx, o));
    if ((tid & 31) == 0) red_max[tid >> 5] = mx;
    __syncthreads();
    mx = red_max[0];
    #pragma unroll
    for (int w = 1; w < 8; ++w) mx = fmaxf(mx, red_max[w]);

    float sum = 0.f;
    #pragma unroll
    for (int i = 0; i < 9; ++i) {
        float e = __expf(SCALE_ * (v[i] - mx));
        v[i] = e;
        sum += e;
    }
    #pragma unroll
    for (int o = 16; o > 0; o >>= 1)
        sum += __shfl_xor_sync(0xffffffffu, sum, o);
    if ((tid & 31) == 0) red_sum[tid >> 5] = sum;
    __syncthreads();
    sum = red_sum[0];
    #pragma unroll
    for (int w = 1; w < 8; ++w) sum += red_sum[w];

    const float inv = 1.f / sum;
    #pragma unroll
    for (int i = 0; i < 9; ++i)
        p[tid + i * 256] = v[i] * inv;
}

// ---------------- launch ------------------------------------------------------
extern "C" void kernel_launch(void* const* d_in, const int* in_sizes, int n_in,
                              void* d_out, int out_size)
{
    (void)in_sizes; (void)n_in; (void)out_size;

    const float* x    = (const float*)d_in[0];
    const float* x_h  = (const float*)d_in[1];
    const float* x_v  = (const float*)d_in[2];
    const float* Wa   = (const float*)d_in[3];
    const float* ba   = (const float*)d_in[4];
    const float* ga   = (const float*)d_in[5];
    const float* ta   = (const float*)d_in[6];
    const float* Wv   = (const float*)d_in[7];
    const float* bv   = (const float*)d_in[8];
    const float* gv   = (const float*)d_in[9];
    const float* tv   = (const float*)d_in[10];
    const float* Wgav = (const float*)d_in[11];
    const float* bgav = (const float*)d_in[12];
    const float* Wgah = (const float*)d_in[13];
    const float* bgah = (const float*)d_in[14];
    const float* Wfav = (const float*)d_in[15];
    const float* bfav = (const float*)d_in[16];
    const float* Wfah = (const float*)d_in[17];
    const float* bfah = (const float*)d_in[18];

    float *fa, *fv, *fh, *gav, *gah, *o, *S;
    cudaGetSymbolAddress((void**)&fa,  g_fa);
    cudaGetSymbolAddress((void**)&fv,  g_fv);
    cudaGetSymbolAddress((void**)&fh,  g_fh);
    cudaGetSymbolAddress((void**)&gav, g_gav);
    cudaGetSymbolAddress((void**)&gah, g_gah);
    cudaGetSymbolAddress((void**)&o,   g_o);
    cudaGetSymbolAddress((void**)&S,   g_S);

    float* out_h = (float*)d_out;                              // first tuple element
    float* out_v = (float*)d_out + (long long)B_ * C_ * N_;    // second tuple element

    const long long sX   = (long long)C_   * N_;   // per-batch x stride
    const long long sMid = (long long)MID_ * N_;   // per-batch [128,2304] stride
    const long long sS   = (long long)N_   * N_;

    dim3 blk(256);
    dim3 gProj(N_ / 128, 1, B_);        // M=128
    dim3 gLog (N_ / 128, N_ / 128, B_); // M=N=2304
    dim3 gAttn(N_ / 128, 1, B_);        // M=128
    dim3 gOut (N_ / 128, C_ / 128, B_); // M=512

    // --- projections (conv1x1): out[b,m,n] = sum_c W[m,c] x[b,c,n] ---
    gemm_k<false,1><<<gProj, blk>>>(Wa,   x,   fa,  MID_, N_, C_, C_, N_, N_,
                                    0, sX, sMid, ba, ga, ta, nullptr, 0);
    gemm_k<false,1><<<gProj, blk>>>(Wv,   x_v, fv,  MID_, N_, C_, C_, N_, N_,
                                    0, sX, sMid, bv, gv, tv, nullptr, 0);
    gemm_k<false,1><<<gProj, blk>>>(Wv,   x_h, fh,  MID_, N_, C_, C_, N_, N_,
                                    0, sX, sMid, bv, gv, tv, nullptr, 0);
    gemm_k<false,2><<<gProj, blk>>>(Wgav, x,   gav, MID_, N_, C_, C_, N_, N_,
                                    0, sX, sMid, bgav, nullptr, nullptr, nullptr, 0);
    gemm_k<false,2><<<gProj, blk>>>(Wgah, x,   gah, MID_, N_, C_, C_, N_, N_,
                                    0, sX, sMid, bgah, nullptr, nullptr, nullptr, 0);

    // ================= v branch =================
    // S[i,j] = sum_m fv[m,i] fa[m,j]
    gemm_k<true,0><<<gLog, blk>>>(fv, fa, S, N_, N_, MID_, N_, N_, N_,
                                  sMid, sMid, sS, nullptr, nullptr, nullptr, nullptr, 0);
    softmax_k<<<B_ * N_, 256>>>(S);
    // o[m,j] = sum_n gav[m,n] A[n,j]
    gemm_k<false,0><<<gAttn, blk>>>(gav, S, o, MID_, N_, N_, N_, N_, N_,
                                    sMid, sS, sMid, nullptr, nullptr, nullptr, nullptr, 0);
    // out_v[c,n] = sum_m Wfav[c,m] o[m,n] + bfav[c] + x[c,n]
    gemm_k<false,3><<<gOut, blk>>>(Wfav, o, out_v, C_, N_, MID_, MID_, N_, N_,
                                   0, sMid, sX, bfav, nullptr, nullptr, x, sX);

    // ================= h branch =================
    gemm_k<true,0><<<gLog, blk>>>(fh, fa, S, N_, N_, MID_, N_, N_, N_,
                                  sMid, sMid, sS, nullptr, nullptr, nullptr, nullptr, 0);
    softmax_k<<<B_ * N_, 256>>>(S);
    gemm_k<false,0><<<gAttn, blk>>>(gah, S, o, MID_, N_, N_, N_, N_, N_,
                                    sMid, sS, sMid, nullptr, nullptr, nullptr, nullptr, 0);
    gemm_k<false,3><<<gOut, blk>>>(Wfah, o, out_h, C_, N_, MID_, MID_, N_, N_,
                                   0, sMid, sX, bfah, nullptr, nullptr, x, sX);
}

// round 3
// speedup vs baseline: 1.0005x; 1.0005x over previous
#include <cuda_runtime.h>
#include <math.h>

// Problem constants
#define B_  8
#define C_  512
#define MID_ 128
#define N_  2304           // H*W = 48*48
static const float EPS_ = 1e-5f;
static const float SCALE_ = 0.08838834764831845f;  // MID^-0.5

// ---------------- scratch (device globals; no cudaMalloc allowed) -------------
__device__ float g_fa [B_ * MID_ * N_];
__device__ float g_fv [B_ * MID_ * N_];
__device__ float g_fh [B_ * MID_ * N_];
__device__ float g_gav[B_ * MID_ * N_];
__device__ float g_gah[B_ * MID_ * N_];
__device__ float g_o  [B_ * MID_ * N_];
__device__ float g_S  [(long long)B_ * N_ * N_];   // 170 MB, reused for both attentions

// ---------------- generic tiled SGEMM ----------------------------------------
// C[m,n] = sum_k A(m,k) * B(k,n)   (per-batch via blockIdx.z and strides)
// TA=false: A row-major [M,K], element A[m*lda+k]
// TA=true : A stored [K,M],    element A[k*lda+m]   (for f^T f logits)
// B always row-major [K,N]: B[k*ldb+n].
// EPI: 0 = none, 1 = BN+ReLU (bias,gamma,beta), 2 = +bias, 3 = +bias +residual
// All dims are multiples of the tile sizes for this problem (no bounds checks).
template<bool TA, int EPI>
__global__ __launch_bounds__(256)
void gemm_k(const float* __restrict__ A, const float* __restrict__ Bp,
            float* __restrict__ C,
            int M, int N, int K, int lda, int ldb, int ldc,
            long long sA, long long sB, long long sC,
            const float* __restrict__ bias,
            const float* __restrict__ gamma,
            const float* __restrict__ beta,
            const float* __restrict__ res, long long sRes)
{
    constexpr int BM = 128, BN = 128, BK = 16;
    __shared__ __align__(16) float As[BK][BM + 4];
    __shared__ __align__(16) float Bs[BK][BN];

    const int bz = blockIdx.z;
    A  += (long long)bz * sA;
    Bp += (long long)bz * sB;
    C  += (long long)bz * sC;
    const float* R = (EPI == 3) ? (res + (long long)bz * sRes) : nullptr;

    const int bm = blockIdx.y * BM;
    const int bn = blockIdx.x * BN;
    const int tid = threadIdx.x;
    const int tx = tid & 15;        // 0..15 -> 8 cols each
    const int ty = tid >> 4;        // 0..15 -> 8 rows each

    float acc[8][8];
    #pragma unroll
    for (int i = 0; i < 8; ++i)
        #pragma unroll
        for (int j = 0; j < 8; ++j) acc[i][j] = 0.f;

    for (int k0 = 0; k0 < K; k0 += BK) {
        // ---- load A tile into As[k][m] ----
        if (TA) {
            const int kr = tid >> 4;          // 0..15
            const int mc = (tid & 15) * 4;    // 0..60
            #pragma unroll
            for (int h = 0; h < 2; ++h) {
                float4 v = *reinterpret_cast<const float4*>(
                    &A[(long long)(k0 + kr) * lda + bm + mc + h * 64]);
                *reinterpret_cast<float4*>(&As[kr][mc + h * 64]) = v;
            }
        } else {
            const int mr = tid >> 2;          // 0..63
            const int kc = (tid & 3) * 4;     // 0..12
            #pragma unroll
            for (int h = 0; h < 2; ++h) {
                float4 v = *reinterpret_cast<const float4*>(
                    &A[(long long)(bm + mr + h * 64) * lda + k0 + kc]);
                As[kc + 0][mr + h * 64] = v.x;
                As[kc + 1][mr + h * 64] = v.y;
                As[kc + 2][mr + h * 64] = v.z;
                As[kc + 3][mr + h * 64] = v.w;
            }
        }
        // ---- load B tile ----
        {
            const int kr = tid >> 4;
            const int nc = (tid & 15) * 4;
            #pragma unroll
            for (int h = 0; h < 2; ++h) {
                float4 v = *reinterpret_cast<const float4*>(
                    &Bp[(long long)(k0 + kr) * ldb + bn + nc + h * 64]);
                *reinterpret_cast<float4*>(&Bs[kr][nc + h * 64]) = v;
            }
        }
        __syncthreads();

        #pragma unroll
        for (int k = 0; k < BK; ++k) {
            float a[8], b[8];
            *reinterpret_cast<float4*>(&a[0]) = *reinterpret_cast<const float4*>(&As[k][ty * 8]);
            *reinterpret_cast<float4*>(&a[4]) = *reinterpret_cast<const float4*>(&As[k][ty * 8 + 4]);
            *reinterpret_cast<float4*>(&b[0]) = *reinterpret_cast<const float4*>(&Bs[k][tx * 8]);
            *reinterpret_cast<float4*>(&b[4]) = *reinterpret_cast<const float4*>(&Bs[k][tx * 8 + 4]);
            #pragma unroll
            for (int i = 0; i < 8; ++i)
                #pragma unroll
                for (int j = 0; j < 8; ++j)
                    acc[i][j] = fmaf(a[i], b[j], acc[i][j]);
        }
        __syncthreads();
    }

    // ---- epilogue ----
    #pragma unroll
    for (int i = 0; i < 8; ++i) {
        const int row = bm + ty * 8 + i;
        float bi = 0.f, sc = 1.f, sh = 0.f;
        if (EPI == 1) {
            bi = bias[row];
            sc = gamma[row] * rsqrtf(1.f + EPS_);
            sh = beta[row];
        } else if (EPI >= 2) {
            bi = bias[row];
        }
        const int col = bn + tx * 8;
        float out[8];
        #pragma unroll
        for (int j = 0; j < 8; ++j) {
            float v = acc[i][j];
            if (EPI == 1)      v = fmaxf(fmaf(v + bi, sc, sh), 0.f);
            else if (EPI == 2) v = v + bi;
            else if (EPI == 3) v = v + bi + R[(long long)row * ldc + col + j];
            out[j] = v;
        }
        *reinterpret_cast<float4*>(&C[(long long)row * ldc + col])     = *reinterpret_cast<float4*>(&out[0]);
        *reinterpret_cast<float4*>(&C[(long long)row * ldc + col + 4]) = *reinterpret_cast<float4*>(&out[4]);
    }
}

// ---------------- row softmax over scale*S, in place --------------------------
// one block per row; 2304 = 9 * 256
__global__ __launch_bounds__(256)
void softmax_k(float* __restrict__ S)
{
    const long long row = blockIdx.x;
    float* p = S + row * (long long)N_;
    const int tid = threadIdx.x;

    float v[9];
    float mx = -1e30f;
    #pragma unroll
    for (int i = 0; i < 9; ++i) {
        v[i] = p[tid + i * 256];
        mx = fmaxf(mx, v[i]);
    }

    __shared__ float red_max[8];
    __shared__ float red_sum[8];

    #pragma unroll
    for (int o = 16; o > 0; o >>= 1)
        mx = fmaxf(mx, __shfl_xor_sync(0xffffffffu, mx, o));
    if ((tid & 31) == 0) red_max[tid >> 5] = mx;
    __syncthreads();
    mx = red_max[0];
    #pragma unroll
    for (int w = 1; w < 8; ++w) mx = fmaxf(mx, red_max[w]);

    float sum = 0.f;
    #pragma unroll
    for (int i = 0; i < 9; ++i) {
        float e = __expf(SCALE_ * (v[i] - mx));
        v[i] = e;
        sum += e;
    }
    #pragma unroll
    for (int o = 16; o > 0; o >>= 1)
        sum += __shfl_xor_sync(0xffffffffu, sum, o);
    if ((tid & 31) == 0) red_sum[tid >> 5] = sum;
    __syncthreads();
    sum = red_sum[0];
    #pragma unroll
    for (int w = 1; w < 8; ++w) sum += red_sum[w];

    const float inv = 1.f / sum;
    #pragma unroll
    for (int i = 0; i < 9; ++i)
        p[tid + i * 256] = v[i] * inv;
}

// ---------------- launch ------------------------------------------------------
extern "C" void kernel_launch(void* const* d_in, const int* in_sizes, int n_in,
                              void* d_out, int out_size)
{
    (void)in_sizes; (void)n_in; (void)out_size;

    const float* x    = (const float*)d_in[0];
    const float* x_h  = (const float*)d_in[1];
    const float* x_v  = (const float*)d_in[2];
    const float* Wa   = (const float*)d_in[3];
    const float* ba   = (const float*)d_in[4];
    const float* ga   = (const float*)d_in[5];
    const float* ta   = (const float*)d_in[6];
    const float* Wv   = (const float*)d_in[7];
    const float* bv   = (const float*)d_in[8];
    const float* gv   = (const float*)d_in[9];
    const float* tv   = (const float*)d_in[10];
    const float* Wgav = (const float*)d_in[11];
    const float* bgav = (const float*)d_in[12];
    const float* Wgah = (const float*)d_in[13];
    const float* bgah = (const float*)d_in[14];
    const float* Wfav = (const float*)d_in[15];
    const float* bfav = (const float*)d_in[16];
    const float* Wfah = (const float*)d_in[17];
    const float* bfah = (const float*)d_in[18];

    float *fa, *fv, *fh, *gav, *gah, *o, *S;
    cudaGetSymbolAddress((void**)&fa,  g_fa);
    cudaGetSymbolAddress((void**)&fv,  g_fv);
    cudaGetSymbolAddress((void**)&fh,  g_fh);
    cudaGetSymbolAddress((void**)&gav, g_gav);
    cudaGetSymbolAddress((void**)&gah, g_gah);
    cudaGetSymbolAddress((void**)&o,   g_o);
    cudaGetSymbolAddress((void**)&S,   g_S);

    float* out_h = (float*)d_out;                              // first tuple element
    float* out_v = (float*)d_out + (long long)B_ * C_ * N_;    // second tuple element

    const long long sX   = (long long)C_   * N_;   // per-batch x stride
    const long long sMid = (long long)MID_ * N_;   // per-batch [128,2304] stride
    const long long sS   = (long long)N_   * N_;

    dim3 blk(256);
    dim3 gProj(N_ / 128, 1, B_);        // M=128
    dim3 gLog (N_ / 128, N_ / 128, B_); // M=N=2304
    dim3 gAttn(N_ / 128, 1, B_);        // M=128
    dim3 gOut (N_ / 128, C_ / 128, B_); // M=512

    // --- projections (conv1x1): out[b,m,n] = sum_c W[m,c] x[b,c,n] ---
    gemm_k<false,1><<<gProj, blk>>>(Wa,   x,   fa,  MID_, N_, C_, C_, N_, N_,
                                    0, sX, sMid, ba, ga, ta, nullptr, 0);
    gemm_k<false,1><<<gProj, blk>>>(Wv,   x_v, fv,  MID_, N_, C_, C_, N_, N_,
                                    0, sX, sMid, bv, gv, tv, nullptr, 0);
    gemm_k<false,1><<<gProj, blk>>>(Wv,   x_h, fh,  MID_, N_, C_, C_, N_, N_,
                                    0, sX, sMid, bv, gv, tv, nullptr, 0);
    gemm_k<false,2><<<gProj, blk>>>(Wgav, x,   gav, MID_, N_, C_, C_, N_, N_,
                                    0, sX, sMid, bgav, nullptr, nullptr, nullptr, 0);
    gemm_k<false,2><<<gProj, blk>>>(Wgah, x,   gah, MID_, N_, C_, C_, N_, N_,
                                    0, sX, sMid, bgah, nullptr, nullptr, nullptr, 0);

    // ================= v branch =================
    // S[i,j] = sum_m fv[m,i] fa[m,j]
    gemm_k<true,0><<<gLog, blk>>>(fv, fa, S, N_, N_, MID_, N_, N_, N_,
                                  sMid, sMid, sS, nullptr, nullptr, nullptr, nullptr, 0);
    softmax_k<<<B_ * N_, 256>>>(S);
    // o[m,j] = sum_n gav[m,n] A[n,j]
    gemm_k<false,0><<<gAttn, blk>>>(gav, S, o, MID_, N_, N_, N_, N_, N_,
                                    sMid, sS, sMid, nullptr, nullptr, nullptr, nullptr, 0);
    // out_v[c,n] = sum_m Wfav[c,m] o[m,n] + bfav[c] + x[c,n]
    gemm_k<false,3><<<gOut, blk>>>(Wfav, o, out_v, C_, N_, MID_, MID_, N_, N_,
                                   0, sMid, sX, bfav, nullptr, nullptr, x, sX);

    // ================= h branch =================
    gemm_k<true,0><<<gLog, blk>>>(fh, fa, S, N_, N_, MID_, N_, N_, N_,
                                  sMid, sMid, sS, nullptr, nullptr, nullptr, nullptr, 0);
    softmax_k<<<B_ * N_, 256>>>(S);
    gemm_k<false,0><<<gAttn, blk>>>(gah, S, o, MID_, N_, N_, N_, N_, N_,
                                    sMid, sS, sMid, nullptr, nullptr, nullptr, nullptr, 0);
    gemm_k<false,3><<<gOut, blk>>>(Wfah, o, out_h, C_, N_, MID_, MID_, N_, N_,
                                   0, sMid, sX, bfah, nullptr, nullptr, x, sX);
}

// round 6
// speedup vs baseline: 1.5466x; 1.5457x over previous
#include <cuda_runtime.h>
#include <cstdint>
#include <math.h>

#define B_   8
#define C_   512
#define MID_ 128
#define N_   2304
#define SCALE_f 0.08838834764831845f

// ---------------- scratch ------------------------------------------------------
__device__ float g_xT [3LL * B_ * N_ * C_];    // [t][b][n][c]  t: 0=x 1=x_h 2=x_v
__device__ float g_fT [3LL * B_ * N_ * MID_];  // [t][b][n][mid] t: 0=fa 1=fv 2=fh
__device__ float g_g  [2LL * B_ * MID_ * N_];  // [t][b][mid][n] t: 0=gav 1=gah
__device__ float g_Lt [(long long)B_ * N_ * N_];   // Lt[b][j][i] = L[i][j]
__device__ float g_oT [(long long)B_ * N_ * MID_]; // oT[b][j][m]
__device__ float g_id [B_ * N_];                   // 1/denominator per row i

// ---------------- helpers ------------------------------------------------------
// fast exp: exp(x) = 2^(x*log2e); poly is Taylor of 2^f on [-0.5,0.5]
__device__ __forceinline__ float fexp(float x) {
    float y = x * 1.4426950408889634f;
    float j = rintf(y);
    float f = y - j;
    float p = 0.0013333558f;
    p = fmaf(p, f, 0.0096181291f);
    p = fmaf(p, f, 0.0555041087f);
    p = fmaf(p, f, 0.2402265070f);
    p = fmaf(p, f, 0.6931471806f);
    p = fmaf(p, f, 1.0f);
    return __int_as_float(__float_as_int(p) + (((int)j) << 23));
}
__device__ __forceinline__ uint32_t to_tf32(float v) {
    uint32_t r;
    asm("cvt.rna.tf32.f32 %0, %1;" : "=r"(r) : "f"(v));
    return r;
}

// ---------------- tf32 mma.sync GEMM -------------------------------------------
// D tile [128,128] of  D = A(M,K) * B(N,K)^T,  both K-major row-major.
// EPI: 0 none; 1 col-wise BN+ReLU; 2 +bias[row]; 3 +bias[row]+res[row][col]
// TRA==1: A element -> fexp(SCALE*v) * vec[k]   (fused softmax for apply GEMM)
#define PITCH 36        // floats per SMEM row (conflict-free)
#define WORDS_TILE (128 * PITCH)

template<int EPI, int TRA>
__global__ void __launch_bounds__(256)
mma_gemm(const float* __restrict__ Ag, const float* __restrict__ Bg,
         float* __restrict__ Cg, int K, int lda, int ldb, int ldc,
         long long sA, long long sB, long long sC,
         const float* __restrict__ bias, const float* __restrict__ gamma,
         const float* __restrict__ beta,
         const float* __restrict__ res, long long sRes,
         const float* __restrict__ vec)
{
    extern __shared__ uint32_t sm[];   // As0 As1 Bs0 Bs1, each 128*36 words

    const int tid  = threadIdx.x;
    const int lane = tid & 31;
    const int wid  = tid >> 5;
    const int wm   = wid & 3;          // 4 m-blocks of 32
    const int wn   = wid >> 2;         // 2 n-blocks of 64
    const int gid  = lane >> 2;        // groupID
    const int tig  = lane & 3;         // threadID_in_group
    const int bz   = blockIdx.z;
    const int bm   = blockIdx.y * 128, bn = blockIdx.x * 128;

    const float* Arow = Ag + (long long)bz * sA + (long long)bm * lda;
    const float* Brow = Bg + (long long)bz * sB + (long long)bn * ldb;
    const float* vecB = TRA ? (vec + (long long)bz * N_) : nullptr;

    const int lr = tid >> 3;            // 0..31 (staging row base)
    const int lc = (tid & 7) * 4;       // 0..28 (staging col)

    float d[2][8][4];
    #pragma unroll
    for (int t = 0; t < 2; ++t)
        #pragma unroll
        for (int j = 0; j < 8; ++j)
            #pragma unroll
            for (int c = 0; c < 4; ++c) d[t][j][c] = 0.f;

    const int nch = K >> 5;
    float4 ra[4], rb[4];

    // ---- staging lambdas ----
    auto ld_chunk = [&](int k0) {
        #pragma unroll
        for (int it = 0; it < 4; ++it) {
            ra[it] = *(const float4*)(Arow + (long long)(lr + it * 32) * lda + k0 + lc);
            rb[it] = *(const float4*)(Brow + (long long)(lr + it * 32) * ldb + k0 + lc);
        }
    };
    auto st_chunk = [&](int buf, int k0) {
        uint32_t* As = sm + (buf ? WORDS_TILE : 0);
        uint32_t* Bs = sm + 2 * WORDS_TILE + (buf ? WORDS_TILE : 0);
        float m0 = 1.f, m1 = 1.f, m2 = 1.f, m3 = 1.f;
        if (TRA) {
            const float* q = vecB + k0 + lc;
            m0 = q[0]; m1 = q[1]; m2 = q[2]; m3 = q[3];
        }
        #pragma unroll
        for (int it = 0; it < 4; ++it) {
            float4 w = ra[it];
            if (TRA) {
                w.x = fexp(SCALE_f * w.x) * m0; w.y = fexp(SCALE_f * w.y) * m1;
                w.z = fexp(SCALE_f * w.z) * m2; w.w = fexp(SCALE_f * w.w) * m3;
            }
            *(uint4*)&As[(lr + it * 32) * PITCH + lc] =
                make_uint4(to_tf32(w.x), to_tf32(w.y), to_tf32(w.z), to_tf32(w.w));
            float4 v = rb[it];
            *(uint4*)&Bs[(lr + it * 32) * PITCH + lc] =
                make_uint4(to_tf32(v.x), to_tf32(v.y), to_tf32(v.z), to_tf32(v.w));
        }
    };

    ld_chunk(0);
    st_chunk(0, 0);

    for (int ch = 0; ch < nch; ++ch) {
        __syncthreads();
        if (ch + 1 < nch) ld_chunk((ch + 1) << 5);

        const uint32_t* As = sm + ((ch & 1) ? WORDS_TILE : 0);
        const uint32_t* Bs = sm + 2 * WORDS_TILE + ((ch & 1) ? WORDS_TILE : 0);

        #pragma unroll
        for (int kk = 0; kk < 4; ++kk) {
            const int k = kk * 8;
            uint32_t a[2][4];
            #pragma unroll
            for (int t = 0; t < 2; ++t) {
                const int r0 = wm * 32 + t * 16 + gid;
                a[t][0] = As[(r0    ) * PITCH + k + tig];
                a[t][1] = As[(r0 + 8) * PITCH + k + tig];
                a[t][2] = As[(r0    ) * PITCH + k + tig + 4];
                a[t][3] = As[(r0 + 8) * PITCH + k + tig + 4];
            }
            #pragma unroll
            for (int j = 0; j < 8; ++j) {
                const int n0 = wn * 64 + j * 8 + gid;
                uint32_t b0 = Bs[n0 * PITCH + k + tig];
                uint32_t b1 = Bs[n0 * PITCH + k + tig + 4];
                #pragma unroll
                for (int t = 0; t < 2; ++t) {
                    asm volatile(
                        "mma.sync.aligned.m16n8k8.row.col.f32.tf32.tf32.f32 "
                        "{%0,%1,%2,%3},{%4,%5,%6,%7},{%8,%9},{%0,%1,%2,%3};"
                        : "+f"(d[t][j][0]), "+f"(d[t][j][1]),
                          "+f"(d[t][j][2]), "+f"(d[t][j][3])
                        : "r"(a[t][0]), "r"(a[t][1]), "r"(a[t][2]), "r"(a[t][3]),
                          "r"(b0), "r"(b1));
                }
            }
        }
        if (ch + 1 < nch) st_chunk((ch + 1) & 1, (ch + 1) << 5);
    }

    // ---- epilogue: direct to gmem (float2 stores) ----
    float* Cb = Cg + (long long)bz * sC;
    const float* Rb = (EPI == 3) ? (res + (long long)bz * sRes) : nullptr;
    const float rs = rsqrtf(1.f + 1e-5f);

    #pragma unroll
    for (int t = 0; t < 2; ++t) {
        #pragma unroll
        for (int j = 0; j < 8; ++j) {
            const int cc = bn + wn * 64 + j * 8 + tig * 2;
            #pragma unroll
            for (int h = 0; h < 2; ++h) {           // h=0 -> row, h=1 -> row+8
                const int rr = bm + wm * 32 + t * 16 + gid + h * 8;
                float v0 = d[t][j][h * 2 + 0];
                float v1 = d[t][j][h * 2 + 1];
                if (EPI == 1) {
                    float s0 = gamma[cc] * rs, s1 = gamma[cc + 1] * rs;
                    v0 = fmaxf(fmaf(v0 + bias[cc],     s0, beta[cc]),     0.f);
                    v1 = fmaxf(fmaf(v1 + bias[cc + 1], s1, beta[cc + 1]), 0.f);
                } else if (EPI == 2) {
                    v0 += bias[rr]; v1 += bias[rr];
                } else if (EPI == 3) {
                    float2 r2 = *(const float2*)(Rb + (long long)rr * ldc + cc);
                    v0 += bias[rr] + r2.x; v1 += bias[rr] + r2.y;
                }
                *(float2*)(Cb + (long long)rr * ldc + cc) = make_float2(v0, v1);
            }
        }
    }
}

// ---------------- 32x32 tiled transpose: [C,N] -> [N,C], 3 tensors x B --------
__global__ __launch_bounds__(256)
void transpose_k(const float* __restrict__ x, const float* __restrict__ xh,
                 const float* __restrict__ xv, float* __restrict__ out)
{
    __shared__ float t[32][33];
    const int z = blockIdx.z;           // 0..23
    const int tsel = z / B_, b = z % B_;
    const float* src = (tsel == 0) ? x : (tsel == 1) ? xh : xv;
    src += (long long)b * C_ * N_;
    float* dst = out + (long long)z * N_ * C_;
    const int n0 = blockIdx.x * 32, c0 = blockIdx.y * 32;
    const int tx = threadIdx.x & 31, ty = threadIdx.x >> 5;  // 32x8
    #pragma unroll
    for (int k = 0; k < 4; ++k)
        t[ty + k * 8][tx] = src[(long long)(c0 + ty + k * 8) * N_ + n0 + tx];
    __syncthreads();
    #pragma unroll
    for (int k = 0; k < 4; ++k)
        dst[(long long)(n0 + ty + k * 8) * C_ + c0 + tx] = t[tx][ty + k * 8];
}

// ------- column stats: invd[i] = 1 / sum_j exp(s*Lt[j,i])  (logits >= 0) -------
__global__ __launch_bounds__(256)
void col_stats(const float* __restrict__ Lt, float* __restrict__ invd)
{
    const int b = blockIdx.y;
    const int i = blockIdx.x * 256 + threadIdx.x;
    const float* p = Lt + (long long)b * N_ * N_ + i;
    float s0 = 0.f, s1 = 0.f, s2 = 0.f, s3 = 0.f;
    for (int j = 0; j < N_; j += 8) {
        float v0 = p[(long long)(j + 0) * N_], v1 = p[(long long)(j + 1) * N_];
        float v2 = p[(long long)(j + 2) * N_], v3 = p[(long long)(j + 3) * N_];
        float v4 = p[(long long)(j + 4) * N_], v5 = p[(long long)(j + 5) * N_];
        float v6 = p[(long long)(j + 6) * N_], v7 = p[(long long)(j + 7) * N_];
        s0 += fexp(SCALE_f * v0); s1 += fexp(SCALE_f * v1);
        s2 += fexp(SCALE_f * v2); s3 += fexp(SCALE_f * v3);
        s0 += fexp(SCALE_f * v4); s1 += fexp(SCALE_f * v5);
        s2 += fexp(SCALE_f * v6); s3 += fexp(SCALE_f * v7);
    }
    invd[b * N_ + i] = 1.f / ((s0 + s1) + (s2 + s3));
}

// ---------------- launch ------------------------------------------------------
extern "C" void kernel_launch(void* const* d_in, const int* in_sizes, int n_in,
                              void* d_out, int out_size)
{
    (void)in_sizes; (void)n_in; (void)out_size;
    const float* x    = (const float*)d_in[0];
    const float* x_h  = (const float*)d_in[1];
    const float* x_v  = (const float*)d_in[2];
    const float* Wa   = (const float*)d_in[3];
    const float* ba   = (const float*)d_in[4];
    const float* ga   = (const float*)d_in[5];
    const float* ta   = (const float*)d_in[6];
    const float* Wv   = (const float*)d_in[7];
    const float* bv   = (const float*)d_in[8];
    const float* gv   = (const float*)d_in[9];
    const float* tv   = (const float*)d_in[10];
    const float* Wgav = (const float*)d_in[11];
    const float* bgav = (const float*)d_in[12];
    const float* Wgah = (const float*)d_in[13];
    const float* bgah = (const float*)d_in[14];
    const float* Wfav = (const float*)d_in[15];
    const float* bfav = (const float*)d_in[16];
    const float* Wfah = (const float*)d_in[17];
    const float* bfah = (const float*)d_in[18];

    float *xT, *fT, *g, *Lt, *oT, *id;
    cudaGetSymbolAddress((void**)&xT, g_xT);
    cudaGetSymbolAddress((void**)&fT, g_fT);
    cudaGetSymbolAddress((void**)&g,  g_g);
    cudaGetSymbolAddress((void**)&Lt, g_Lt);
    cudaGetSymbolAddress((void**)&oT, g_oT);
    cudaGetSymbolAddress((void**)&id, g_id);

    const long long segX = (long long)B_ * N_ * C_;
    const long long segF = (long long)B_ * N_ * MID_;
    const long long segG = (long long)B_ * MID_ * N_;
    float* xT0 = xT;   float* xT1 = xT + segX;  float* xT2 = xT + 2 * segX;
    float* faT = fT;   float* fvT = fT + segF;  float* fhT = fT + 2 * segF;
    float* gav = g;    float* gah = g + segG;

    float* out_h = (float*)d_out;
    float* out_v = (float*)d_out + (long long)B_ * C_ * N_;

    const long long sX = (long long)C_ * N_;
    const long long sF = (long long)N_ * MID_;
    const long long sG = (long long)MID_ * N_;
    const long long sS = (long long)N_ * N_;

    const int SMEM = 4 * WORDS_TILE * 4;   // 73728 bytes
    cudaFuncSetAttribute(mma_gemm<1,0>, cudaFuncAttributeMaxDynamicSharedMemorySize, SMEM);
    cudaFuncSetAttribute(mma_gemm<2,0>, cudaFuncAttributeMaxDynamicSharedMemorySize, SMEM);
    cudaFuncSetAttribute(mma_gemm<0,0>, cudaFuncAttributeMaxDynamicSharedMemorySize, SMEM);
    cudaFuncSetAttribute(mma_gemm<0,1>, cudaFuncAttributeMaxDynamicSharedMemorySize, SMEM);
    cudaFuncSetAttribute(mma_gemm<3,0>, cudaFuncAttributeMaxDynamicSharedMemorySize, SMEM);

    dim3 blk(256);
    transpose_k<<<dim3(N_/32, C_/32, 3 * B_), blk>>>(x, x_h, x_v, xT);

    // projections -> fT[n][mid]  (EPI1: column-wise BN+ReLU)
    dim3 gF(1, N_/128, B_);
    mma_gemm<1,0><<<gF, blk, SMEM>>>(xT0, Wa, faT, C_, C_, C_, MID_,
                                     sX, 0, sF, ba, ga, ta, nullptr, 0, nullptr);
    mma_gemm<1,0><<<gF, blk, SMEM>>>(xT2, Wv, fvT, C_, C_, C_, MID_,
                                     sX, 0, sF, bv, gv, tv, nullptr, 0, nullptr);
    mma_gemm<1,0><<<gF, blk, SMEM>>>(xT1, Wv, fhT, C_, C_, C_, MID_,
                                     sX, 0, sF, bv, gv, tv, nullptr, 0, nullptr);
    // g projections -> g[mid][n]  (EPI2: +bias[row])
    dim3 gG(N_/128, 1, B_);
    mma_gemm<2,0><<<gG, blk, SMEM>>>(Wgav, xT0, gav, C_, C_, C_, N_,
                                     0, sX, sG, bgav, nullptr, nullptr, nullptr, 0, nullptr);
    mma_gemm<2,0><<<gG, blk, SMEM>>>(Wgah, xT0, gah, C_, C_, C_, N_,
                                     0, sX, sG, bgah, nullptr, nullptr, nullptr, 0, nullptr);

    dim3 gL(N_/128, N_/128, B_);
    dim3 gA(1, N_/128, B_);
    dim3 gO(N_/128, C_/128, B_);

    // ===== v branch =====
    mma_gemm<0,0><<<gL, blk, SMEM>>>(faT, fvT, Lt, MID_, MID_, MID_, N_,
                                     sF, sF, sS, nullptr, nullptr, nullptr, nullptr, 0, nullptr);
    col_stats<<<dim3(N_/256, B_), blk>>>(Lt, id);
    mma_gemm<0,1><<<gA, blk, SMEM>>>(Lt, gav, oT, N_, N_, N_, MID_,
                                     sS, sG, sF, nullptr, nullptr, nullptr, nullptr, 0, id);
    mma_gemm<3,0><<<gO, blk, SMEM>>>(Wfav, oT, out_v, MID_, MID_, MID_, N_,
                                     0, sF, sX, bfav, nullptr, nullptr, x, sX, nullptr);

    // ===== h branch =====
    mma_gemm<0,0><<<gL, blk, SMEM>>>(faT, fhT, Lt, MID_, MID_, MID_, N_,
                                     sF, sF, sS, nullptr, nullptr, nullptr, nullptr, 0, nullptr);
    col_stats<<<dim3(N_/256, B_), blk>>>(Lt, id);
    mma_gemm<0,1><<<gA, blk, SMEM>>>(Lt, gah, oT, N_, N_, N_, MID_,
                                     sS, sG, sF, nullptr, nullptr, nullptr, nullptr, 0, id);
    mma_gemm<3,0><<<gO, blk, SMEM>>>(Wfah, oT, out_h, MID_, MID_, MID_, N_,
                                     0, sF, sX, bfah, nullptr, nullptr, x, sX, nullptr);
}

// round 9
// speedup vs baseline: 2.0715x; 1.3394x over previous
#include <cuda_runtime.h>
#include <cuda_bf16.h>
#include <cstdint>
#include <math.h>

#define B_   8
#define C_   512
#define MID_ 128
#define N_   2304
#define SCALE_f 0.08838834764831845f

typedef __nv_bfloat16  bf16;
typedef __nv_bfloat162 bf162;

// ---------------- scratch (device globals) -------------------------------------
__device__ bf16  g_xT [3LL * B_ * N_ * C_];     // [t][b][n][c]  t:0=x 1=x_h 2=x_v
__device__ bf16  g_fT [3LL * B_ * N_ * MID_];   // [t][b][n][mid] 0=fa 1=fv 2=fh
__device__ bf16  g_gp [2LL * B_ * MID_ * N_];   // [t][b][mid][n] 0=gav 1=gah
__device__ bf16  g_Lt [(long long)B_ * N_ * N_];    // Lt[b][j][i] = L[i][j]
__device__ bf16  g_oT [(long long)B_ * N_ * MID_];  // oT[b][j][m]
__device__ float g_oP [2LL * B_ * N_ * MID_];       // split-K partials (fp32)
__device__ float g_id [B_ * N_];                    // 1/denominator per row i
__device__ bf16  g_Wb [6 * 65536];                  // converted weights

// ---------------- helpers -------------------------------------------------------
__device__ __forceinline__ uint32_t smem_u32(const void* p) {
    uint32_t a;
    asm("{ .reg .u64 t; cvta.to.shared.u64 t, %1; cvt.u32.u64 %0, t; }" : "=r"(a) : "l"(p));
    return a;
}
// fast exp: 2^(x*log2e), FFMA-only
__device__ __forceinline__ float fexp(float x) {
    float y = x * 1.4426950408889634f;
    float j = rintf(y);
    float f = y - j;
    float p = 0.0013333558f;
    p = fmaf(p, f, 0.0096181291f);
    p = fmaf(p, f, 0.0555041087f);
    p = fmaf(p, f, 0.2402265070f);
    p = fmaf(p, f, 0.6931471806f);
    p = fmaf(p, f, 1.0f);
    return __int_as_float(__float_as_int(p) + (((int)j) << 23));
}

#define LDSM4(R, a)                                                           \
    asm volatile("ldmatrix.sync.aligned.m8n8.x4.shared.b16 {%0,%1,%2,%3}, [%4];" \
        : "=r"((R)[0]), "=r"((R)[1]), "=r"((R)[2]), "=r"((R)[3]) : "r"(a))

#define MMA16(D, A, b0, b1)                                                   \
    asm volatile("mma.sync.aligned.m16n8k16.row.col.f32.bf16.bf16.f32 "       \
        "{%0,%1,%2,%3},{%4,%5,%6,%7},{%8,%9},{%0,%1,%2,%3};"                  \
        : "+f"((D)[0]), "+f"((D)[1]), "+f"((D)[2]), "+f"((D)[3])              \
        : "r"((A)[0]), "r"((A)[1]), "r"((A)[2]), "r"((A)[3]), "r"(b0), "r"(b1))

#define STS128(a, v)                                                          \
    asm volatile("st.shared.v4.b32 [%0], {%1,%2,%3,%4};"                      \
        :: "r"(a), "r"((v).x), "r"((v).y), "r"((v).z), "r"((v).w) : "memory")

// SMEM: A bufs at 0 / 10240, B bufs at 20480 / 30720 (pitch 40 bf16 = 80 B/row)
#define TILEB 10240

// ---------------- generic bf16 GEMM: tile[128,128] of A(M,K) x B(N,K)^T --------
// EPI: 0 plain->bf16; 1 col BN+ReLU->bf16; 2 +bias[row]->bf16; 3 +bias[row]+res->f32
template<int EPI>
__global__ void __launch_bounds__(256, 2)
mma_bf16(const bf16* __restrict__ Ag, const bf16* __restrict__ Bg,
         void* __restrict__ Cg, int K, int lda, int ldb, int ldc,
         long long sA, long long sB, long long sC,
         const float* __restrict__ bias, const float* __restrict__ gamma,
         const float* __restrict__ beta,
         const float* __restrict__ res, long long sRes)
{
    __shared__ __align__(16) char sm[4 * TILEB];
    const uint32_t sb = smem_u32(sm);
    const int tid = threadIdx.x, lane = tid & 31, wid = tid >> 5;
    const int wm = wid & 3, wn = wid >> 2, gid = lane >> 2, tig = lane & 3;
    const int bz = blockIdx.z;
    const int bm = blockIdx.y * 128, bn = blockIdx.x * 128;

    const bf16* Arow = Ag + (long long)bz * sA + (long long)bm * lda;
    const bf16* Brow = Bg + (long long)bz * sB + (long long)bn * ldb;

    const int lrow = tid >> 1, lhalf = tid & 1;
    const bf16* gA = Arow + (long long)lrow * lda + lhalf * 16;
    const bf16* gB = Brow + (long long)lrow * ldb + lhalf * 16;
    const uint32_t stA = sb + lrow * 80 + lhalf * 32;
    const uint32_t stB = stA + 2 * TILEB;

    const uint32_t aAddr = sb + (wm * 32 + (lane & 15)) * 80 + (lane >> 4) * 16;
    const uint32_t bAddr = sb + 2 * TILEB + (wn * 64 + (lane & 15)) * 80 + (lane >> 4) * 16;

    float d[2][8][4];
    #pragma unroll
    for (int t = 0; t < 2; ++t)
        #pragma unroll
        for (int j = 0; j < 8; ++j)
            #pragma unroll
            for (int c = 0; c < 4; ++c) d[t][j][c] = 0.f;

    uint4 ra0, ra1, rb0, rb1;
    const int nch = K >> 5;

    auto LD = [&](int k0) {
        ra0 = *(const uint4*)(gA + k0);  ra1 = *(const uint4*)(gA + k0 + 8);
        rb0 = *(const uint4*)(gB + k0);  rb1 = *(const uint4*)(gB + k0 + 8);
    };
    auto ST = [&](int buf) {
        uint32_t a = stA + buf * TILEB, b = stB + buf * TILEB;
        STS128(a, ra0); STS128(a + 16, ra1);
        STS128(b, rb0); STS128(b + 16, rb1);
    };

    LD(0); ST(0);
    for (int ch = 0; ch < nch; ++ch) {
        __syncthreads();
        if (ch + 1 < nch) LD((ch + 1) << 5);
        const uint32_t ab = aAddr + (ch & 1) * TILEB;
        const uint32_t bb = bAddr + (ch & 1) * TILEB;
        #pragma unroll
        for (int kk = 0; kk < 2; ++kk) {
            uint32_t A0[4], A1[4], Bv[4][4];
            LDSM4(A0, ab + kk * 32);
            LDSM4(A1, ab + 1280 + kk * 32);
            #pragma unroll
            for (int jp = 0; jp < 4; ++jp) LDSM4(Bv[jp], bb + jp * 1280 + kk * 32);
            #pragma unroll
            for (int j = 0; j < 8; ++j) {
                const int jp = j >> 1, o = j & 1;
                MMA16(d[0][j], A0, Bv[jp][o], Bv[jp][o + 2]);
                MMA16(d[1][j], A1, Bv[jp][o], Bv[jp][o + 2]);
            }
        }
        if (ch + 1 < nch) ST((ch + 1) & 1);
    }

    // ---- epilogue ----
    const float rs = rsqrtf(1.f + 1e-5f);
    if (EPI == 3) {
        float* Cb = (float*)Cg + (long long)bz * sC;
        const float* Rb = res + (long long)bz * sRes;
        #pragma unroll
        for (int t = 0; t < 2; ++t)
            #pragma unroll
            for (int j = 0; j < 8; ++j) {
                const int cc = bn + wn * 64 + j * 8 + tig * 2;
                #pragma unroll
                for (int h = 0; h < 2; ++h) {
                    const int rr = bm + wm * 32 + t * 16 + gid + h * 8;
                    float2 r2 = *(const float2*)(Rb + (long long)rr * ldc + cc);
                    float v0 = d[t][j][h * 2]     + bias[rr] + r2.x;
                    float v1 = d[t][j][h * 2 + 1] + bias[rr] + r2.y;
                    *(float2*)(Cb + (long long)rr * ldc + cc) = make_float2(v0, v1);
                }
            }
    } else {
        bf16* Cb = (bf16*)Cg + (long long)bz * sC;
        #pragma unroll
        for (int t = 0; t < 2; ++t)
            #pragma unroll
            for (int j = 0; j < 8; ++j) {
                const int cc = bn + wn * 64 + j * 8 + tig * 2;
                float b0 = 0.f, b1 = 0.f, s0 = 1.f, s1 = 1.f, e0 = 0.f, e1 = 0.f;
                if (EPI == 1) {
                    b0 = bias[cc]; b1 = bias[cc + 1];
                    s0 = gamma[cc] * rs; s1 = gamma[cc + 1] * rs;
                    e0 = beta[cc]; e1 = beta[cc + 1];
                }
                #pragma unroll
                for (int h = 0; h < 2; ++h) {
                    const int rr = bm + wm * 32 + t * 16 + gid + h * 8;
                    float v0 = d[t][j][h * 2], v1 = d[t][j][h * 2 + 1];
                    if (EPI == 1) {
                        v0 = fmaxf(fmaf(v0 + b0, s0, e0), 0.f);
                        v1 = fmaxf(fmaf(v1 + b1, s1, e1), 0.f);
                    } else if (EPI == 2) {
                        v0 += bias[rr]; v1 += bias[rr];
                    }
                    *(bf162*)(Cb + (long long)rr * ldc + cc) = __floats2bfloat162_rn(v0, v1);
                }
            }
    }
}

// --------- apply GEMM (split-K=2): oP[split] = exp(s*Lt)*invd  x  g^T ----------
__global__ void __launch_bounds__(256)
mma_apply(const bf16* __restrict__ Ltp, const bf16* __restrict__ Gm,
          float* __restrict__ oP, const float* __restrict__ invd)
{
    __shared__ __align__(16) char sm[4 * TILEB];
    const uint32_t sb = smem_u32(sm);
    const int tid = threadIdx.x, lane = tid & 31, wid = tid >> 5;
    const int wm = wid & 3, wn = wid >> 2, gid = lane >> 2, tig = lane & 3;
    const int split = blockIdx.x, bz = blockIdx.z;
    const int bm = blockIdx.y * 128;

    const bf16*  Arow = Ltp + (long long)bz * N_ * N_ + (long long)bm * N_;
    const bf16*  Brow = Gm  + (long long)bz * MID_ * N_;
    const float* vec  = invd + (long long)bz * N_;

    const int lrow = tid >> 1, lhalf = tid & 1;
    const bf16* gA = Arow + (long long)lrow * N_ + lhalf * 16;
    const bf16* gB = Brow + (long long)lrow * N_ + lhalf * 16;
    const uint32_t stA = sb + lrow * 80 + lhalf * 32;
    const uint32_t stB = stA + 2 * TILEB;

    const uint32_t aAddr = sb + (wm * 32 + (lane & 15)) * 80 + (lane >> 4) * 16;
    const uint32_t bAddr = sb + 2 * TILEB + (wn * 64 + (lane & 15)) * 80 + (lane >> 4) * 16;

    float d[2][8][4];
    #pragma unroll
    for (int t = 0; t < 2; ++t)
        #pragma unroll
        for (int j = 0; j < 8; ++j)
            #pragma unroll
            for (int c = 0; c < 4; ++c) d[t][j][c] = 0.f;

    uint4 ra0, ra1, rb0, rb1;
    const int kbase = split * (N_ / 2);
    const int nch = (N_ / 2) >> 5;       // 36

    auto LD = [&](int k0) {
        ra0 = *(const uint4*)(gA + k0);  ra1 = *(const uint4*)(gA + k0 + 8);
        rb0 = *(const uint4*)(gB + k0);  rb1 = *(const uint4*)(gB + k0 + 8);
    };
    auto XF = [&](uint4 u, const float4 f0, const float4 f1) -> uint4 {
        bf162* h = (bf162*)&u;
        uint4 o; uint32_t* po = (uint32_t*)&o;
        const float m[8] = {f0.x, f0.y, f0.z, f0.w, f1.x, f1.y, f1.z, f1.w};
        #pragma unroll
        for (int q = 0; q < 4; ++q) {
            float2 f = __bfloat1622float2(h[q]);
            f.x = fexp(SCALE_f * f.x) * m[2 * q];
            f.y = fexp(SCALE_f * f.y) * m[2 * q + 1];
            bf162 r = __floats2bfloat162_rn(f.x, f.y);
            po[q] = *(uint32_t*)&r;
        }
        return o;
    };
    auto ST = [&](int buf, int k0) {
        const float* vp = vec + k0 + lhalf * 16;
        float4 f0 = *(const float4*)(vp);
        float4 f1 = *(const float4*)(vp + 4);
        float4 f2 = *(const float4*)(vp + 8);
        float4 f3 = *(const float4*)(vp + 12);
        uint4 ta0 = XF(ra0, f0, f1);
        uint4 ta1 = XF(ra1, f2, f3);
        uint32_t a = stA + buf * TILEB, b = stB + buf * TILEB;
        STS128(a, ta0); STS128(a + 16, ta1);
        STS128(b, rb0); STS128(b + 16, rb1);
    };

    LD(kbase); ST(0, kbase);
    for (int ch = 0; ch < nch; ++ch) {
        __syncthreads();
        if (ch + 1 < nch) LD(kbase + ((ch + 1) << 5));
        const uint32_t ab = aAddr + (ch & 1) * TILEB;
        const uint32_t bb = bAddr + (ch & 1) * TILEB;
        #pragma unroll
        for (int kk = 0; kk < 2; ++kk) {
            uint32_t A0[4], A1[4], Bv[4][4];
            LDSM4(A0, ab + kk * 32);
            LDSM4(A1, ab + 1280 + kk * 32);
            #pragma unroll
            for (int jp = 0; jp < 4; ++jp) LDSM4(Bv[jp], bb + jp * 1280 + kk * 32);
            #pragma unroll
            for (int j = 0; j < 8; ++j) {
                const int jp = j >> 1, o = j & 1;
                MMA16(d[0][j], A0, Bv[jp][o], Bv[jp][o + 2]);
                MMA16(d[1][j], A1, Bv[jp][o], Bv[jp][o + 2]);
            }
        }
        if (ch + 1 < nch) ST((ch + 1) & 1, kbase + ((ch + 1) << 5));
    }

    float* Cb = oP + ((long long)(split * gridDim.z + bz)) * N_ * MID_;
    #pragma unroll
    for (int t = 0; t < 2; ++t)
        #pragma unroll
        for (int j = 0; j < 8; ++j) {
            const int cc = wn * 64 + j * 8 + tig * 2;
            #pragma unroll
            for (int h = 0; h < 2; ++h) {
                const int rr = bm + wm * 32 + t * 16 + gid + h * 8;
                *(float2*)(Cb + (long long)rr * MID_ + cc) =
                    make_float2(d[t][j][h * 2], d[t][j][h * 2 + 1]);
            }
        }
}

// ---------------- split-K reduce: oT = bf16(oP[0] + oP[1]) ---------------------
__global__ void __launch_bounds__(256)
reduce_oT(const float* __restrict__ oP, bf16* __restrict__ oT)
{
    const long long idx = (long long)blockIdx.x * 256 + threadIdx.x;  // float4 units
    const long long seg = (long long)B_ * N_ * MID_;                  // 2359296
    float4 a = ((const float4*)oP)[idx];
    float4 b = ((const float4*)(oP + seg))[idx];
    bf162 r0 = __floats2bfloat162_rn(a.x + b.x, a.y + b.y);
    bf162 r1 = __floats2bfloat162_rn(a.z + b.z, a.w + b.w);
    ((bf162*)oT)[idx * 2]     = r0;
    ((bf162*)oT)[idx * 2 + 1] = r1;
}

// ---------------- column stats: invd[i] = 1/sum_j exp(s*Lt[j,i]) ---------------
__global__ void __launch_bounds__(128)
col_stats(const bf16* __restrict__ Lt, float* __restrict__ invd)
{
    const int b = blockIdx.y;
    const int i2 = blockIdx.x * 128 + threadIdx.x;   // bf162 column pair
    const bf162* p = (const bf162*)(Lt + (long long)b * N_ * N_) + i2;
    float s0 = 0.f, s1 = 0.f, s2 = 0.f, s3 = 0.f;
    #pragma unroll 4
    for (int j = 0; j < N_; j += 2) {
        float2 f0 = __bfloat1622float2(p[(long long)j * (N_ / 2)]);
        float2 f1 = __bfloat1622float2(p[(long long)(j + 1) * (N_ / 2)]);
        s0 += fexp(SCALE_f * f0.x); s1 += fexp(SCALE_f * f0.y);
        s2 += fexp(SCALE_f * f1.x); s3 += fexp(SCALE_f * f1.y);
    }
    invd[b * N_ + 2 * i2]     = 1.f / (s0 + s2);
    invd[b * N_ + 2 * i2 + 1] = 1.f / (s1 + s3);
}

// ---------------- transpose [C,N] -> [N,C] as bf16, 3 tensors x B --------------
__global__ void __launch_bounds__(256)
transpose_k(const float* __restrict__ x, const float* __restrict__ xh,
            const float* __restrict__ xv, bf16* __restrict__ out)
{
    __shared__ float t[32][33];
    const int z = blockIdx.z;
    const int tsel = z / B_, b = z % B_;
    const float* src = (tsel == 0) ? x : (tsel == 1) ? xh : xv;
    src += (long long)b * C_ * N_;
    bf16* dst = out + (long long)z * N_ * C_;
    const int n0 = blockIdx.x * 32, c0 = blockIdx.y * 32;
    const int tx = threadIdx.x & 31, ty = threadIdx.x >> 5;
    #pragma unroll
    for (int k = 0; k < 4; ++k)
        t[ty + k * 8][tx] = src[(long long)(c0 + ty + k * 8) * N_ + n0 + tx];
    __syncthreads();
    #pragma unroll
    for (int k = 0; k < 4; ++k)
        dst[(long long)(n0 + ty + k * 8) * C_ + c0 + tx] =
            __float2bfloat16(t[tx][ty + k * 8]);
}

// ---------------- weight conversion: six 65536-element fp32 -> bf16 ------------
__global__ void __launch_bounds__(256)
conv_w(const float* w0, const float* w1, const float* w2,
       const float* w3, const float* w4, const float* w5, bf16* out)
{
    const int idx = blockIdx.x * 256 + threadIdx.x;
    const int seg = idx >> 16, off = idx & 65535;
    const float* s = (seg == 0) ? w0 : (seg == 1) ? w1 : (seg == 2) ? w2
                   : (seg == 3) ? w3 : (seg == 4) ? w4 : w5;
    out[idx] = __float2bfloat16(s[off]);
}

// ---------------- launch --------------------------------------------------------
extern "C" void kernel_launch(void* const* d_in, const int* in_sizes, int n_in,
                              void* d_out, int out_size)
{
    (void)in_sizes; (void)n_in; (void)out_size;
    const float* x    = (const float*)d_in[0];
    const float* x_h  = (const float*)d_in[1];
    const float* x_v  = (const float*)d_in[2];
    const float* Wa   = (const float*)d_in[3];
    const float* ba   = (const float*)d_in[4];
    const float* ga   = (const float*)d_in[5];
    const float* ta   = (const float*)d_in[6];
    const float* Wv   = (const float*)d_in[7];
    const float* bv   = (const float*)d_in[8];
    const float* gv   = (const float*)d_in[9];
    const float* tv   = (const float*)d_in[10];
    const float* Wgav = (const float*)d_in[11];
    const float* bgav = (const float*)d_in[12];
    const float* Wgah = (const float*)d_in[13];
    const float* bgah = (const float*)d_in[14];
    const float* Wfav = (const float*)d_in[15];
    const float* bfav = (const float*)d_in[16];
    const float* Wfah = (const float*)d_in[17];
    const float* bfah = (const float*)d_in[18];

    bf16 *xT, *fT, *gp, *Lt, *oT, *Wb;
    float *oP, *id;
    cudaGetSymbolAddress((void**)&xT, g_xT);
    cudaGetSymbolAddress((void**)&fT, g_fT);
    cudaGetSymbolAddress((void**)&gp, g_gp);
    cudaGetSymbolAddress((void**)&Lt, g_Lt);
    cudaGetSymbolAddress((void**)&oT, g_oT);
    cudaGetSymbolAddress((void**)&oP, g_oP);
    cudaGetSymbolAddress((void**)&id, g_id);
    cudaGetSymbolAddress((void**)&Wb, g_Wb);

    const long long segX = (long long)B_ * N_ * C_;
    const long long segF = (long long)B_ * N_ * MID_;
    const long long segG = (long long)B_ * MID_ * N_;
    bf16* xT0 = xT;  bf16* xT1 = xT + segX;  bf16* xT2 = xT + 2 * segX;
    bf16* faT = fT;  bf16* fvT = fT + segF;  bf16* fhT = fT + 2 * segF;
    bf16* gav = gp;  bf16* gah = gp + segG;
    bf16* Wba   = Wb;            bf16* Wbv   = Wb + 65536;
    bf16* Wbgav = Wb + 131072;   bf16* Wbgah = Wb + 196608;
    bf16* Wbfav = Wb + 262144;   bf16* Wbfah = Wb + 327680;

    float* out_h = (float*)d_out;
    float* out_v = (float*)d_out + (long long)B_ * C_ * N_;

    const long long sX = (long long)C_ * N_;
    const long long sF = (long long)N_ * MID_;
    const long long sG = (long long)MID_ * N_;
    const long long sS = (long long)N_ * N_;

    dim3 blk(256);
    conv_w<<<1536, blk>>>(Wa, Wv, Wgav, Wgah, Wfav, Wfah, Wb);
    transpose_k<<<dim3(N_/32, C_/32, 3 * B_), blk>>>(x, x_h, x_v, xT);

    // projections -> fT[n][mid] (EPI1)
    dim3 gF(1, N_/128, B_);
    mma_bf16<1><<<gF, blk>>>(xT0, Wba, faT, C_, C_, C_, MID_,
                             sX, 0, sF, ba, ga, ta, nullptr, 0);
    mma_bf16<1><<<gF, blk>>>(xT2, Wbv, fvT, C_, C_, C_, MID_,
                             sX, 0, sF, bv, gv, tv, nullptr, 0);
    mma_bf16<1><<<gF, blk>>>(xT1, Wbv, fhT, C_, C_, C_, MID_,
                             sX, 0, sF, bv, gv, tv, nullptr, 0);
    // g projections -> g[mid][n] (EPI2)
    dim3 gG(N_/128, 1, B_);
    mma_bf16<2><<<gG, blk>>>(Wbgav, xT0, gav, C_, C_, C_, N_,
                             0, sX, sG, bgav, nullptr, nullptr, nullptr, 0);
    mma_bf16<2><<<gG, blk>>>(Wbgah, xT0, gah, C_, C_, C_, N_,
                             0, sX, sG, bgah, nullptr, nullptr, nullptr, 0);

    dim3 gL(N_/128, N_/128, B_);
    dim3 gAp(2, N_/128, B_);            // split-K = 2
    dim3 gO(N_/128, C_/128, B_);
    dim3 gR((B_ * N_ * MID_) / 4 / 256);

    // ===== v branch =====
    mma_bf16<0><<<gL, blk>>>(faT, fvT, Lt, MID_, MID_, MID_, N_,
                             sF, sF, sS, nullptr, nullptr, nullptr, nullptr, 0);
    col_stats<<<dim3(N_/256, B_), 128>>>(Lt, id);
    mma_apply<<<gAp, blk>>>(Lt, gav, oP, id);
    reduce_oT<<<gR, blk>>>(oP, oT);
    mma_bf16<3><<<gO, blk>>>(Wbfav, oT, out_v, MID_, MID_, MID_, N_,
                             0, sF, sX, bfav, nullptr, nullptr, x, sX);

    // ===== h branch =====
    mma_bf16<0><<<gL, blk>>>(faT, fhT, Lt, MID_, MID_, MID_, N_,
                             sF, sF, sS, nullptr, nullptr, nullptr, nullptr, 0);
    col_stats<<<dim3(N_/256, B_), 128>>>(Lt, id);
    mma_apply<<<gAp, blk>>>(Lt, gah, oP, id);
    reduce_oT<<<gR, blk>>>(oP, oT);
    mma_bf16<3><<<gO, blk>>>(Wbfah, oT, out_h, MID_, MID_, MID_, N_,
                             0, sF, sX, bfah, nullptr, nullptr, x, sX);
}

// round 11
// speedup vs baseline: 3.8292x; 1.8485x over previous
#include <cuda_runtime.h>
#include <cuda_bf16.h>
#include <cstdint>
#include <math.h>

#define B_   8
#define C_   512
#define MID_ 128
#define N_   2304
#define SCALE_f 0.08838834764831845f

typedef __nv_bfloat16  bf16;
typedef __nv_bfloat162 bf162;

// ---------------- scratch (device globals) -------------------------------------
__device__ bf16  g_xT [3LL * B_ * N_ * C_];       // [t][b][n][c]  t:0=x 1=x_h 2=x_v
__device__ bf16  g_fT [3LL * B_ * N_ * MID_];     // [t][b][n][mid] 0=fa 1=fv 2=fh
__device__ bf16  g_gp [2LL * B_ * MID_ * N_];     // [t][b][mid][n] 0=gav 1=gah
__device__ bf16  g_Lt [2LL * B_ * N_ * N_];       // P[br][b][j][i] = exp(s*L[i][j])
__device__ bf16  g_oT [2LL * B_ * N_ * MID_];     // oT[br][b][j][m]
__device__ float g_D  [2 * B_ * N_];              // denominators -> reciprocals
__device__ bf16  g_Wb [6 * 65536];                // converted weights

// ---------------- helpers -------------------------------------------------------
__device__ __forceinline__ uint32_t smem_u32(const void* p) {
    uint32_t a;
    asm("{ .reg .u64 t; cvta.to.shared.u64 t, %1; cvt.u32.u64 %0, t; }" : "=r"(a) : "l"(p));
    return a;
}
// fast exp: 2^(x*log2e), FFMA-only
__device__ __forceinline__ float fexp(float x) {
    float y = x * 1.4426950408889634f;
    float j = rintf(y);
    float f = y - j;
    float p = 0.0013333558f;
    p = fmaf(p, f, 0.0096181291f);
    p = fmaf(p, f, 0.0555041087f);
    p = fmaf(p, f, 0.2402265070f);
    p = fmaf(p, f, 0.6931471806f);
    p = fmaf(p, f, 1.0f);
    return __int_as_float(__float_as_int(p) + (((int)j) << 23));
}

#define LDSM4(R, a)                                                           \
    asm volatile("ldmatrix.sync.aligned.m8n8.x4.shared.b16 {%0,%1,%2,%3}, [%4];" \
        : "=r"((R)[0]), "=r"((R)[1]), "=r"((R)[2]), "=r"((R)[3]) : "r"(a))

#define MMA16(D, A, b0, b1)                                                   \
    asm volatile("mma.sync.aligned.m16n8k16.row.col.f32.bf16.bf16.f32 "       \
        "{%0,%1,%2,%3},{%4,%5,%6,%7},{%8,%9},{%0,%1,%2,%3};"                  \
        : "+f"((D)[0]), "+f"((D)[1]), "+f"((D)[2]), "+f"((D)[3])              \
        : "r"((A)[0]), "r"((A)[1]), "r"((A)[2]), "r"((A)[3]), "r"(b0), "r"(b1))

#define STS128(a, v)                                                          \
    asm volatile("st.shared.v4.b32 [%0], {%1,%2,%3,%4};"                      \
        :: "r"(a), "r"((v).x), "r"((v).y), "r"((v).z), "r"((v).w) : "memory")

#define TILEB 10240   // A bufs at 0/10240, B bufs at 20480/30720; pitch 40 bf16

// ======= shared GEMM prologue/mainloop macros (identical fragment layout) =======
#define GEMM_VARS()                                                           \
    const int tid = threadIdx.x, lane = tid & 31, wid = tid >> 5;             \
    const int wm = wid & 3, wn = wid >> 2, gid = lane >> 2, tig = lane & 3;   \
    const int lrow = tid >> 1, lhalf = tid & 1;                               \
    float d[2][8][4];                                                         \
    _Pragma("unroll")                                                         \
    for (int t = 0; t < 2; ++t)                                               \
        _Pragma("unroll")                                                     \
        for (int j = 0; j < 8; ++j)                                           \
            _Pragma("unroll")                                                 \
            for (int c = 0; c < 4; ++c) d[t][j][c] = 0.f;

#define GEMM_ADDRS(sb)                                                        \
    const uint32_t stA = (sb) + lrow * 80 + lhalf * 32;                       \
    const uint32_t stB = stA + 2 * TILEB;                                     \
    const uint32_t aAddr = (sb) + (wm * 32 + (lane & 15)) * 80 + (lane >> 4) * 16; \
    const uint32_t bAddr = (sb) + 2 * TILEB + (wn * 64 + (lane & 15)) * 80 + (lane >> 4) * 16;

#define GEMM_MAINLOOP(nch, LD, ST)                                            \
    LD(0); ST(0, 0);                                                          \
    for (int ch = 0; ch < (nch); ++ch) {                                      \
        __syncthreads();                                                      \
        if (ch + 1 < (nch)) LD((ch + 1) << 5);                                \
        const uint32_t ab = aAddr + (ch & 1) * TILEB;                         \
        const uint32_t bb = bAddr + (ch & 1) * TILEB;                         \
        _Pragma("unroll")                                                     \
        for (int kk = 0; kk < 2; ++kk) {                                      \
            uint32_t A0[4], A1[4], Bv[4][4];                                  \
            LDSM4(A0, ab + kk * 32);                                          \
            LDSM4(A1, ab + 1280 + kk * 32);                                   \
            _Pragma("unroll")                                                 \
            for (int jp = 0; jp < 4; ++jp) LDSM4(Bv[jp], bb + jp * 1280 + kk * 32); \
            _Pragma("unroll")                                                 \
            for (int j = 0; j < 8; ++j) {                                     \
                const int jp = j >> 1, o = j & 1;                             \
                MMA16(d[0][j], A0, Bv[jp][o], Bv[jp][o + 2]);                 \
                MMA16(d[1][j], A1, Bv[jp][o], Bv[jp][o + 2]);                 \
            }                                                                 \
        }                                                                     \
        if (ch + 1 < (nch)) ST((ch + 1) & 1, (ch + 1) << 5);                  \
    }

// ---------------- generic bf16 GEMM (projections & out-conv) -------------------
// EPI: 1 col BN+ReLU->bf16; 2 +bias[row]->bf16; 3 +bias[row]+res->f32
template<int EPI>
__global__ void __launch_bounds__(256, 2)
mma_bf16(const bf16* __restrict__ Ag, const bf16* __restrict__ Bg,
         void* __restrict__ Cg, int K, int lda, int ldb, int ldc,
         long long sA, long long sB, long long sC,
         const float* __restrict__ bias, const float* __restrict__ gamma,
         const float* __restrict__ beta,
         const float* __restrict__ res, long long sRes)
{
    __shared__ __align__(16) char sm[4 * TILEB];
    const uint32_t sb = smem_u32(sm);
    GEMM_VARS();
    const int bz = blockIdx.z;
    const int bm = blockIdx.y * 128, bn = blockIdx.x * 128;

    const bf16* gA = Ag + (long long)bz * sA + (long long)(bm + lrow) * lda + lhalf * 16;
    const bf16* gB = Bg + (long long)bz * sB + (long long)(bn + lrow) * ldb + lhalf * 16;
    GEMM_ADDRS(sb);

    uint4 ra0, ra1, rb0, rb1;
    auto LD = [&](int k0) {
        ra0 = *(const uint4*)(gA + k0);  ra1 = *(const uint4*)(gA + k0 + 8);
        rb0 = *(const uint4*)(gB + k0);  rb1 = *(const uint4*)(gB + k0 + 8);
    };
    auto ST = [&](int buf, int k0) {
        (void)k0;
        uint32_t a = stA + buf * TILEB, b = stB + buf * TILEB;
        STS128(a, ra0); STS128(a + 16, ra1);
        STS128(b, rb0); STS128(b + 16, rb1);
    };
    const int nch = K >> 5;
    GEMM_MAINLOOP(nch, LD, ST);

    const float rs = rsqrtf(1.f + 1e-5f);
    if (EPI == 3) {
        float* Cb = (float*)Cg + (long long)bz * sC;
        const float* Rb = res + (long long)bz * sRes;
        #pragma unroll
        for (int t = 0; t < 2; ++t)
            #pragma unroll
            for (int j = 0; j < 8; ++j) {
                const int cc = bn + wn * 64 + j * 8 + tig * 2;
                #pragma unroll
                for (int h = 0; h < 2; ++h) {
                    const int rr = bm + wm * 32 + t * 16 + gid + h * 8;
                    float2 r2 = *(const float2*)(Rb + (long long)rr * ldc + cc);
                    float v0 = d[t][j][h * 2]     + bias[rr] + r2.x;
                    float v1 = d[t][j][h * 2 + 1] + bias[rr] + r2.y;
                    *(float2*)(Cb + (long long)rr * ldc + cc) = make_float2(v0, v1);
                }
            }
    } else {
        bf16* Cb = (bf16*)Cg + (long long)bz * sC;
        #pragma unroll
        for (int t = 0; t < 2; ++t)
            #pragma unroll
            for (int j = 0; j < 8; ++j) {
                const int cc = bn + wn * 64 + j * 8 + tig * 2;
                float b0 = 0.f, b1 = 0.f, s0 = 1.f, s1 = 1.f, e0 = 0.f, e1 = 0.f;
                if (EPI == 1) {
                    b0 = bias[cc]; b1 = bias[cc + 1];
                    s0 = gamma[cc] * rs; s1 = gamma[cc + 1] * rs;
                    e0 = beta[cc]; e1 = beta[cc + 1];
                }
                #pragma unroll
                for (int h = 0; h < 2; ++h) {
                    const int rr = bm + wm * 32 + t * 16 + gid + h * 8;
                    float v0 = d[t][j][h * 2], v1 = d[t][j][h * 2 + 1];
                    if (EPI == 1) {
                        v0 = fmaxf(fmaf(v0 + b0, s0, e0), 0.f);
                        v1 = fmaxf(fmaf(v1 + b1, s1, e1), 0.f);
                    } else {
                        v0 += bias[rr]; v1 += bias[rr];
                    }
                    *(bf162*)(Cb + (long long)rr * ldc + cc) = __floats2bfloat162_rn(v0, v1);
                }
            }
    }
}

// -------- logits: P = exp(s * faT x fqT^T) stored bf16; D[i] += column sums ----
__global__ void __launch_bounds__(256, 2)
mma_logits(const bf16* __restrict__ faT, const bf16* __restrict__ fqT,
           bf16* __restrict__ Pout, float* __restrict__ Dv)
{
    __shared__ __align__(16) char sm[4 * TILEB];
    const uint32_t sb = smem_u32(sm);
    GEMM_VARS();
    const int bz = blockIdx.z;                  // batch
    const int bm = blockIdx.y * 128, bn = blockIdx.x * 128;
    const long long sF = (long long)N_ * MID_;

    const bf16* gA = faT + (long long)bz * sF + (long long)(bm + lrow) * MID_ + lhalf * 16;
    const bf16* gB = fqT + (long long)bz * sF + (long long)(bn + lrow) * MID_ + lhalf * 16;
    GEMM_ADDRS(sb);

    uint4 ra0, ra1, rb0, rb1;
    auto LD = [&](int k0) {
        ra0 = *(const uint4*)(gA + k0);  ra1 = *(const uint4*)(gA + k0 + 8);
        rb0 = *(const uint4*)(gB + k0);  rb1 = *(const uint4*)(gB + k0 + 8);
    };
    auto ST = [&](int buf, int k0) {
        (void)k0;
        uint32_t a = stA + buf * TILEB, b = stB + buf * TILEB;
        STS128(a, ra0); STS128(a + 16, ra1);
        STS128(b, rb0); STS128(b + 16, rb1);
    };
    GEMM_MAINLOOP(4, LD, ST);                  // K = MID = 128

    bf16*  Cb = Pout + (long long)bz * N_ * N_;
    float* Dp = Dv + bz * N_;
    #pragma unroll
    for (int j = 0; j < 8; ++j) {
        const int cc = bn + wn * 64 + j * 8 + tig * 2;
        float s0 = 0.f, s1 = 0.f;
        #pragma unroll
        for (int t = 0; t < 2; ++t)
            #pragma unroll
            for (int h = 0; h < 2; ++h) {
                const int rr = bm + wm * 32 + t * 16 + gid + h * 8;
                float e0 = fexp(SCALE_f * d[t][j][h * 2]);
                float e1 = fexp(SCALE_f * d[t][j][h * 2 + 1]);
                bf162 r = __floats2bfloat162_rn(e0, e1);
                *(bf162*)(Cb + (long long)rr * N_ + cc) = r;
                float2 f = __bfloat1622float2(r);   // sum the ROUNDED values
                s0 += f.x; s1 += f.y;
            }
        s0 += __shfl_xor_sync(0xffffffffu, s0, 4);
        s0 += __shfl_xor_sync(0xffffffffu, s0, 8);
        s0 += __shfl_xor_sync(0xffffffffu, s0, 16);
        s1 += __shfl_xor_sync(0xffffffffu, s1, 4);
        s1 += __shfl_xor_sync(0xffffffffu, s1, 8);
        s1 += __shfl_xor_sync(0xffffffffu, s1, 16);
        if (gid == 0) {
            atomicAdd(Dp + cc,     s0);
            atomicAdd(Dp + cc + 1, s1);
        }
    }
}

// -------- apply (both branches, z=16): oT = (P * invd[k]) x g^T  ---------------
__global__ void __launch_bounds__(256, 2)
mma_apply(const bf16* __restrict__ Pg, const bf16* __restrict__ gav,
          const bf16* __restrict__ gah, bf16* __restrict__ oTg,
          const float* __restrict__ invd)
{
    __shared__ __align__(16) char sm[4 * TILEB];
    const uint32_t sb = smem_u32(sm);
    GEMM_VARS();
    const int z = blockIdx.z;                   // z = br*8 + b
    const int br = z >> 3, b = z & 7;
    const int bm = blockIdx.y * 128;

    const bf16* gA = Pg + (long long)z * N_ * N_ + (long long)(bm + lrow) * N_ + lhalf * 16;
    const bf16* gB = (br ? gah : gav) + (long long)b * MID_ * N_
                     + (long long)lrow * N_ + lhalf * 16;
    const float* vec = invd + z * N_;
    GEMM_ADDRS(sb);

    uint4 ra0, ra1, rb0, rb1;
    auto LD = [&](int k0) {
        ra0 = *(const uint4*)(gA + k0);  ra1 = *(const uint4*)(gA + k0 + 8);
        rb0 = *(const uint4*)(gB + k0);  rb1 = *(const uint4*)(gB + k0 + 8);
    };
    auto XF = [&](uint4 u, const float* m) -> uint4 {
        bf162* hh = (bf162*)&u;
        uint4 o; uint32_t* po = (uint32_t*)&o;
        #pragma unroll
        for (int q = 0; q < 4; ++q) {
            float2 f = __bfloat1622float2(hh[q]);
            f.x *= m[2 * q]; f.y *= m[2 * q + 1];
            bf162 r = __floats2bfloat162_rn(f.x, f.y);
            po[q] = *(uint32_t*)&r;
        }
        return o;
    };
    auto ST = [&](int buf, int k0) {
        float mv[16];
        *(float4*)(mv)      = *(const float4*)(vec + k0 + lhalf * 16);
        *(float4*)(mv + 4)  = *(const float4*)(vec + k0 + lhalf * 16 + 4);
        *(float4*)(mv + 8)  = *(const float4*)(vec + k0 + lhalf * 16 + 8);
        *(float4*)(mv + 12) = *(const float4*)(vec + k0 + lhalf * 16 + 12);
        uint4 ta0 = XF(ra0, mv);
        uint4 ta1 = XF(ra1, mv + 8);
        uint32_t a = stA + buf * TILEB, bptr = stB + buf * TILEB;
        STS128(a, ta0); STS128(a + 16, ta1);
        STS128(bptr, rb0); STS128(bptr + 16, rb1);
    };
    GEMM_MAINLOOP(N_ / 32, LD, ST);            // 72 chunks

    bf16* Cb = oTg + (long long)z * N_ * MID_;
    #pragma unroll
    for (int t = 0; t < 2; ++t)
        #pragma unroll
        for (int j = 0; j < 8; ++j) {
            const int cc = wn * 64 + j * 8 + tig * 2;
            #pragma unroll
            for (int h = 0; h < 2; ++h) {
                const int rr = bm + wm * 32 + t * 16 + gid + h * 8;
                *(bf162*)(Cb + (long long)rr * MID_ + cc) =
                    __floats2bfloat162_rn(d[t][j][h * 2], d[t][j][h * 2 + 1]);
            }
        }
}

// ---------------- small utility kernels ----------------------------------------
__global__ void __launch_bounds__(256)
zero_D(float* D) { D[blockIdx.x * 256 + threadIdx.x] = 0.f; }

__global__ void __launch_bounds__(256)
invert_D(float* D) {
    const int i = blockIdx.x * 256 + threadIdx.x;
    D[i] = 1.f / D[i];
}

__global__ void __launch_bounds__(256)
transpose_k(const float* __restrict__ x, const float* __restrict__ xh,
            const float* __restrict__ xv, bf16* __restrict__ out)
{
    __shared__ float t[32][33];
    const int z = blockIdx.z;
    const int tsel = z / B_, b = z % B_;
    const float* src = (tsel == 0) ? x : (tsel == 1) ? xh : xv;
    src += (long long)b * C_ * N_;
    bf16* dst = out + (long long)z * N_ * C_;
    const int n0 = blockIdx.x * 32, c0 = blockIdx.y * 32;
    const int tx = threadIdx.x & 31, ty = threadIdx.x >> 5;
    #pragma unroll
    for (int k = 0; k < 4; ++k)
        t[ty + k * 8][tx] = src[(long long)(c0 + ty + k * 8) * N_ + n0 + tx];
    __syncthreads();
    #pragma unroll
    for (int k = 0; k < 4; ++k)
        dst[(long long)(n0 + ty + k * 8) * C_ + c0 + tx] =
            __float2bfloat16(t[tx][ty + k * 8]);
}

__global__ void __launch_bounds__(256)
conv_w(const float* w0, const float* w1, const float* w2,
       const float* w3, const float* w4, const float* w5, bf16* out)
{
    const int idx = blockIdx.x * 256 + threadIdx.x;
    const int seg = idx >> 16, off = idx & 65535;
    const float* s = (seg == 0) ? w0 : (seg == 1) ? w1 : (seg == 2) ? w2
                   : (seg == 3) ? w3 : (seg == 4) ? w4 : w5;
    out[idx] = __float2bfloat16(s[off]);
}

// ---------------- launch --------------------------------------------------------
extern "C" void kernel_launch(void* const* d_in, const int* in_sizes, int n_in,
                              void* d_out, int out_size)
{
    (void)in_sizes; (void)n_in; (void)out_size;
    const float* x    = (const float*)d_in[0];
    const float* x_h  = (const float*)d_in[1];
    const float* x_v  = (const float*)d_in[2];
    const float* Wa   = (const float*)d_in[3];
    const float* ba   = (const float*)d_in[4];
    const float* ga   = (const float*)d_in[5];
    const float* ta   = (const float*)d_in[6];
    const float* Wv   = (const float*)d_in[7];
    const float* bv   = (const float*)d_in[8];
    const float* gv   = (const float*)d_in[9];
    const float* tv   = (const float*)d_in[10];
    const float* Wgav = (const float*)d_in[11];
    const float* bgav = (const float*)d_in[12];
    const float* Wgah = (const float*)d_in[13];
    const float* bgah = (const float*)d_in[14];
    const float* Wfav = (const float*)d_in[15];
    const float* bfav = (const float*)d_in[16];
    const float* Wfah = (const float*)d_in[17];
    const float* bfah = (const float*)d_in[18];

    bf16 *xT, *fT, *gp, *Lt, *oT, *Wb;
    float *Dv;
    cudaGetSymbolAddress((void**)&xT, g_xT);
    cudaGetSymbolAddress((void**)&fT, g_fT);
    cudaGetSymbolAddress((void**)&gp, g_gp);
    cudaGetSymbolAddress((void**)&Lt, g_Lt);
    cudaGetSymbolAddress((void**)&oT, g_oT);
    cudaGetSymbolAddress((void**)&Dv, g_D);
    cudaGetSymbolAddress((void**)&Wb, g_Wb);

    const long long segX = (long long)B_ * N_ * C_;
    const long long segF = (long long)B_ * N_ * MID_;
    const long long segG = (long long)B_ * MID_ * N_;
    const long long segS = (long long)B_ * N_ * N_;
    bf16* xT0 = xT;  bf16* xT1 = xT + segX;  bf16* xT2 = xT + 2 * segX;
    bf16* faT = fT;  bf16* fvT = fT + segF;  bf16* fhT = fT + 2 * segF;
    bf16* gav = gp;  bf16* gah = gp + segG;
    bf16* Wba   = Wb;            bf16* Wbv   = Wb + 65536;
    bf16* Wbgav = Wb + 131072;   bf16* Wbgah = Wb + 196608;
    bf16* Wbfav = Wb + 262144;   bf16* Wbfah = Wb + 327680;

    float* out_h = (float*)d_out;
    float* out_v = (float*)d_out + (long long)B_ * C_ * N_;

    const long long sX = (long long)C_ * N_;
    const long long sF = (long long)N_ * MID_;
    const long long sG = (long long)MID_ * N_;

    dim3 blk(256);
    zero_D<<<(2 * B_ * N_) / 256, blk>>>(Dv);
    conv_w<<<1536, blk>>>(Wa, Wv, Wgav, Wgah, Wfav, Wfah, Wb);
    transpose_k<<<dim3(N_/32, C_/32, 3 * B_), blk>>>(x, x_h, x_v, xT);

    // projections -> fT[n][mid] (EPI1)
    dim3 gF(1, N_/128, B_);
    mma_bf16<1><<<gF, blk>>>(xT0, Wba, faT, C_, C_, C_, MID_,
                             sX, 0, sF, ba, ga, ta, nullptr, 0);
    mma_bf16<1><<<gF, blk>>>(xT2, Wbv, fvT, C_, C_, C_, MID_,
                             sX, 0, sF, bv, gv, tv, nullptr, 0);
    mma_bf16<1><<<gF, blk>>>(xT1, Wbv, fhT, C_, C_, C_, MID_,
                             sX, 0, sF, bv, gv, tv, nullptr, 0);
    // g projections -> g[mid][n] (EPI2)
    dim3 gG(N_/128, 1, B_);
    mma_bf16<2><<<gG, blk>>>(Wbgav, xT0, gav, C_, C_, C_, N_,
                             0, sX, sG, bgav, nullptr, nullptr, nullptr, 0);
    mma_bf16<2><<<gG, blk>>>(Wbgah, xT0, gah, C_, C_, C_, N_,
                             0, sX, sG, bgah, nullptr, nullptr, nullptr, 0);

    // logits (P = exp, D accumulated), per branch
    dim3 gL(N_/128, N_/128, B_);
    mma_logits<<<gL, blk>>>(faT, fvT, Lt,        Dv);           // v branch
    mma_logits<<<gL, blk>>>(faT, fhT, Lt + segS, Dv + B_ * N_); // h branch
    invert_D<<<(2 * B_ * N_) / 256, blk>>>(Dv);

    // apply, both branches in one launch (z = br*8 + b)
    dim3 gA(1, N_/128, 16);
    mma_apply<<<gA, blk>>>(Lt, gav, gah, oT, Dv);

    // output convs + residual
    dim3 gO(N_/128, C_/128, B_);
    mma_bf16<3><<<gO, blk>>>(Wbfav, oT,        out_v, MID_, MID_, MID_, N_,
                             0, sF, sX, bfav, nullptr, nullptr, x, sX);
    mma_bf16<3><<<gO, blk>>>(Wbfah, oT + segF, out_h, MID_, MID_, MID_, N_,
                             0, sF, sX, bfah, nullptr, nullptr, x, sX);
}

// round 12
// speedup vs baseline: 4.2528x; 1.1106x over previous
#include <cuda_runtime.h>
#include <cuda_bf16.h>
#include <cstdint>
#include <math.h>

#define B_   8
#define C_   512
#define MID_ 128
#define N_   2304
#define SCALE_f 0.08838834764831845f

typedef __nv_bfloat16  bf16;
typedef __nv_bfloat162 bf162;

// ---------------- scratch (device globals) -------------------------------------
__device__ bf16  g_xT [3LL * B_ * N_ * C_];       // [t][b][n][c]  t:0=x 1=x_h 2=x_v
__device__ bf16  g_fT [3LL * B_ * N_ * MID_];     // [t][b][n][mid] 0=fa 1=fv 2=fh
__device__ bf16  g_gp [2LL * B_ * MID_ * N_];     // [t][b][mid][n] 0=gav 1=gah
__device__ bf16  g_g2 [2LL * B_ * MID_ * N_];     // g scaled by 1/D
__device__ bf16  g_Lt [2LL * B_ * N_ * N_];       // P[br][b][j][i] = exp(s*L[i][j])
__device__ bf16  g_oT [2LL * B_ * N_ * MID_];     // oT[br][b][j][m]
__device__ float g_D  [2 * B_ * N_];              // row denominators
__device__ bf16  g_Wb [6 * 65536];                // converted weights

// ---------------- helpers -------------------------------------------------------
__device__ __forceinline__ uint32_t smem_u32(const void* p) {
    uint32_t a;
    asm("{ .reg .u64 t; cvta.to.shared.u64 t, %1; cvt.u32.u64 %0, t; }" : "=r"(a) : "l"(p));
    return a;
}
// fast exp: 2^(x*log2e), FFMA-only
__device__ __forceinline__ float fexp(float x) {
    float y = x * 1.4426950408889634f;
    float j = rintf(y);
    float f = y - j;
    float p = 0.0013333558f;
    p = fmaf(p, f, 0.0096181291f);
    p = fmaf(p, f, 0.0555041087f);
    p = fmaf(p, f, 0.2402265070f);
    p = fmaf(p, f, 0.6931471806f);
    p = fmaf(p, f, 1.0f);
    return __int_as_float(__float_as_int(p) + (((int)j) << 23));
}

#define LDSM4(R, a)                                                           \
    asm volatile("ldmatrix.sync.aligned.m8n8.x4.shared.b16 {%0,%1,%2,%3}, [%4];" \
        : "=r"((R)[0]), "=r"((R)[1]), "=r"((R)[2]), "=r"((R)[3]) : "r"(a))

#define MMA16(D, A, b0, b1)                                                   \
    asm volatile("mma.sync.aligned.m16n8k16.row.col.f32.bf16.bf16.f32 "       \
        "{%0,%1,%2,%3},{%4,%5,%6,%7},{%8,%9},{%0,%1,%2,%3};"                  \
        : "+f"((D)[0]), "+f"((D)[1]), "+f"((D)[2]), "+f"((D)[3])              \
        : "r"((A)[0]), "r"((A)[1]), "r"((A)[2]), "r"((A)[3]), "r"(b0), "r"(b1))

#define STS128(a, v)                                                          \
    asm volatile("st.shared.v4.b32 [%0], {%1,%2,%3,%4};"                      \
        :: "r"(a), "r"((v).x), "r"((v).y), "r"((v).z), "r"((v).w) : "memory")

#define TILEB 10240   // A bufs at 0/10240, B bufs at 20480/30720; pitch 40 bf16

// ======= shared GEMM prologue/mainloop macros ===================================
#define GEMM_VARS()                                                           \
    const int tid = threadIdx.x, lane = tid & 31, wid = tid >> 5;             \
    const int wm = wid & 3, wn = wid >> 2, gid = lane >> 2, tig = lane & 3;   \
    const int lrow = tid >> 1, lhalf = tid & 1;                               \
    float d[2][8][4];                                                         \
    _Pragma("unroll")                                                         \
    for (int t = 0; t < 2; ++t)                                               \
        _Pragma("unroll")                                                     \
        for (int j = 0; j < 8; ++j)                                           \
            _Pragma("unroll")                                                 \
            for (int c = 0; c < 4; ++c) d[t][j][c] = 0.f;

#define GEMM_ADDRS(sb)                                                        \
    const uint32_t stA = (sb) + lrow * 80 + lhalf * 32;                       \
    const uint32_t stB = stA + 2 * TILEB;                                     \
    const uint32_t aAddr = (sb) + (wm * 32 + (lane & 15)) * 80 + (lane >> 4) * 16; \
    const uint32_t bAddr = (sb) + 2 * TILEB + (wn * 64 + (lane & 15)) * 80 + (lane >> 4) * 16;

#define GEMM_MAINLOOP(nch, LD, ST)                                            \
    LD(0); ST(0, 0);                                                          \
    for (int ch = 0; ch < (nch); ++ch) {                                      \
        __syncthreads();                                                      \
        if (ch + 1 < (nch)) LD((ch + 1) << 5);                                \
        const uint32_t ab = aAddr + (ch & 1) * TILEB;                         \
        const uint32_t bb = bAddr + (ch & 1) * TILEB;                         \
        _Pragma("unroll")                                                     \
        for (int kk = 0; kk < 2; ++kk) {                                      \
            uint32_t A0[4], A1[4], Bv[4][4];                                  \
            LDSM4(A0, ab + kk * 32);                                          \
            LDSM4(A1, ab + 1280 + kk * 32);                                   \
            _Pragma("unroll")                                                 \
            for (int jp = 0; jp < 4; ++jp) LDSM4(Bv[jp], bb + jp * 1280 + kk * 32); \
            _Pragma("unroll")                                                 \
            for (int j = 0; j < 8; ++j) {                                     \
                const int jp = j >> 1, o = j & 1;                             \
                MMA16(d[0][j], A0, Bv[jp][o], Bv[jp][o + 2]);                 \
                MMA16(d[1][j], A1, Bv[jp][o], Bv[jp][o + 2]);                 \
            }                                                                 \
        }                                                                     \
        if (ch + 1 < (nch)) ST((ch + 1) & 1, (ch + 1) << 5);                  \
    }

#define PLAIN_LD_ST()                                                         \
    uint4 ra0, ra1, rb0, rb1;                                                 \
    auto LD = [&](int k0) {                                                   \
        ra0 = *(const uint4*)(gA + k0);  ra1 = *(const uint4*)(gA + k0 + 8);  \
        rb0 = *(const uint4*)(gB + k0);  rb1 = *(const uint4*)(gB + k0 + 8);  \
    };                                                                        \
    auto ST = [&](int buf, int k0) {                                          \
        (void)k0;                                                             \
        uint32_t a = stA + buf * TILEB, b = stB + buf * TILEB;                \
        STS128(a, ra0); STS128(a + 16, ra1);                                  \
        STS128(b, rb0); STS128(b + 16, rb1);                                  \
    };

// ---------------- merged projections: 5 GEMMs x 8 batches in one launch --------
// z = p*8 + b.  p: 0=fa 1=fv 2=fh (EPI col BN+ReLU), 3=gav 4=gah (EPI row bias)
__global__ void __launch_bounds__(256, 2)
proj_all(const bf16* __restrict__ xT, const bf16* __restrict__ Wb,
         bf16* __restrict__ fT, bf16* __restrict__ gp,
         const float* __restrict__ ba, const float* __restrict__ ga, const float* __restrict__ ta,
         const float* __restrict__ bv, const float* __restrict__ gv, const float* __restrict__ tv,
         const float* __restrict__ bgav, const float* __restrict__ bgah)
{
    __shared__ __align__(16) char sm[4 * TILEB];
    const uint32_t sb = smem_u32(sm);
    GEMM_VARS();
    const int z = blockIdx.z, p = z >> 3, b = z & 7;
    const int bx = blockIdx.x;
    const long long sXb = (long long)N_ * C_;

    const bf16 *gA, *gB;
    int bm, bn;
    if (p < 3) {
        const int tsel = (p == 0) ? 0 : (p == 1 ? 2 : 1);
        bm = bx * 128; bn = 0;
        gA = xT + (long long)(tsel * B_ + b) * sXb + (long long)(bm + lrow) * C_ + lhalf * 16;
        gB = Wb + (p == 0 ? 0 : 65536) + lrow * C_ + lhalf * 16;
    } else {
        bm = 0; bn = bx * 128;
        gA = Wb + 131072 + (p - 3) * 65536 + lrow * C_ + lhalf * 16;
        gB = xT + (long long)b * sXb + (long long)(bn + lrow) * C_ + lhalf * 16;
    }
    GEMM_ADDRS(sb);
    PLAIN_LD_ST();
    GEMM_MAINLOOP(16, LD, ST);      // K = 512

    const float rs = rsqrtf(1.f + 1e-5f);
    if (p < 3) {
        bf16* Cb = fT + (long long)(p * B_ + b) * ((long long)N_ * MID_);
        const float* Bi = (p == 0) ? ba : bv;
        const float* Ga = (p == 0) ? ga : gv;
        const float* Be = (p == 0) ? ta : tv;
        #pragma unroll
        for (int t = 0; t < 2; ++t)
            #pragma unroll
            for (int j = 0; j < 8; ++j) {
                const int cc = wn * 64 + j * 8 + tig * 2;
                const float b0 = Bi[cc],      b1 = Bi[cc + 1];
                const float s0 = Ga[cc] * rs, s1 = Ga[cc + 1] * rs;
                const float e0 = Be[cc],      e1 = Be[cc + 1];
                #pragma unroll
                for (int h = 0; h < 2; ++h) {
                    const int rr = bm + wm * 32 + t * 16 + gid + h * 8;
                    float v0 = fmaxf(fmaf(d[t][j][h * 2]     + b0, s0, e0), 0.f);
                    float v1 = fmaxf(fmaf(d[t][j][h * 2 + 1] + b1, s1, e1), 0.f);
                    *(bf162*)(Cb + (long long)rr * MID_ + cc) = __floats2bfloat162_rn(v0, v1);
                }
            }
    } else {
        bf16* Cb = gp + (long long)((p - 3) * B_ + b) * ((long long)MID_ * N_);
        const float* Bi = (p == 3) ? bgav : bgah;
        #pragma unroll
        for (int t = 0; t < 2; ++t)
            #pragma unroll
            for (int j = 0; j < 8; ++j) {
                const int cc = bn + wn * 64 + j * 8 + tig * 2;
                #pragma unroll
                for (int h = 0; h < 2; ++h) {
                    const int rr = wm * 32 + t * 16 + gid + h * 8;
                    float v0 = d[t][j][h * 2]     + Bi[rr];
                    float v1 = d[t][j][h * 2 + 1] + Bi[rr];
                    *(bf162*)(Cb + (long long)rr * N_ + cc) = __floats2bfloat162_rn(v0, v1);
                }
            }
    }
}

// -------- logits (both branches): P = exp(s*L^T) bf16; D[i] += col sums --------
__global__ void __launch_bounds__(256, 2)
mma_logits(const bf16* __restrict__ faT, const bf16* __restrict__ fvT,
           const bf16* __restrict__ fhT, bf16* __restrict__ Pout,
           float* __restrict__ Dv)
{
    __shared__ __align__(16) char sm[4 * TILEB];
    const uint32_t sb = smem_u32(sm);
    GEMM_VARS();
    const int z = blockIdx.z, br = z >> 3, b = z & 7;
    const int bm = blockIdx.y * 128, bn = blockIdx.x * 128;
    const long long sF = (long long)N_ * MID_;

    const bf16* fq = br ? fhT : fvT;
    const bf16* gA = faT + (long long)b * sF + (long long)(bm + lrow) * MID_ + lhalf * 16;
    const bf16* gB = fq  + (long long)b * sF + (long long)(bn + lrow) * MID_ + lhalf * 16;
    GEMM_ADDRS(sb);
    PLAIN_LD_ST();
    GEMM_MAINLOOP(4, LD, ST);       // K = MID = 128

    bf16*  Cb = Pout + (long long)z * N_ * N_;
    float* Dp = Dv + z * N_;
    #pragma unroll
    for (int j = 0; j < 8; ++j) {
        const int cc = bn + wn * 64 + j * 8 + tig * 2;
        float s0 = 0.f, s1 = 0.f;
        #pragma unroll
        for (int t = 0; t < 2; ++t)
            #pragma unroll
            for (int h = 0; h < 2; ++h) {
                const int rr = bm + wm * 32 + t * 16 + gid + h * 8;
                float e0 = fexp(SCALE_f * d[t][j][h * 2]);
                float e1 = fexp(SCALE_f * d[t][j][h * 2 + 1]);
                bf162 r = __floats2bfloat162_rn(e0, e1);
                *(bf162*)(Cb + (long long)rr * N_ + cc) = r;
                float2 f = __bfloat1622float2(r);   // sum the ROUNDED values
                s0 += f.x; s1 += f.y;
            }
        s0 += __shfl_xor_sync(0xffffffffu, s0, 4);
        s0 += __shfl_xor_sync(0xffffffffu, s0, 8);
        s0 += __shfl_xor_sync(0xffffffffu, s0, 16);
        s1 += __shfl_xor_sync(0xffffffffu, s1, 4);
        s1 += __shfl_xor_sync(0xffffffffu, s1, 8);
        s1 += __shfl_xor_sync(0xffffffffu, s1, 16);
        if (gid == 0) {
            atomicAdd(Dp + cc,     s0);
            atomicAdd(Dp + cc + 1, s1);
        }
    }
}

// -------- apply (both branches): oT = P x g2^T (plain GEMM, z=16) --------------
__global__ void __launch_bounds__(256, 2)
mma_apply(const bf16* __restrict__ Pg, const bf16* __restrict__ g2,
          bf16* __restrict__ oTg)
{
    __shared__ __align__(16) char sm[4 * TILEB];
    const uint32_t sb = smem_u32(sm);
    GEMM_VARS();
    const int z = blockIdx.z;
    const int bm = blockIdx.y * 128;

    const bf16* gA = Pg + (long long)z * N_ * N_ + (long long)(bm + lrow) * N_ + lhalf * 16;
    const bf16* gB = g2 + (long long)z * MID_ * N_ + (long long)lrow * N_ + lhalf * 16;
    GEMM_ADDRS(sb);
    PLAIN_LD_ST();
    GEMM_MAINLOOP(N_ / 32, LD, ST); // 72 chunks

    bf16* Cb = oTg + (long long)z * N_ * MID_;
    #pragma unroll
    for (int t = 0; t < 2; ++t)
        #pragma unroll
        for (int j = 0; j < 8; ++j) {
            const int cc = wn * 64 + j * 8 + tig * 2;
            #pragma unroll
            for (int h = 0; h < 2; ++h) {
                const int rr = bm + wm * 32 + t * 16 + gid + h * 8;
                *(bf162*)(Cb + (long long)rr * MID_ + cc) =
                    __floats2bfloat162_rn(d[t][j][h * 2], d[t][j][h * 2 + 1]);
            }
        }
}

// -------- merged output convs: out = Wf x oT^T + bias + x (z=16) ---------------
__global__ void __launch_bounds__(256, 2)
outconv_all(const bf16* __restrict__ Wb, const bf16* __restrict__ oTg,
            const float* __restrict__ x,
            const float* __restrict__ bfav, const float* __restrict__ bfah,
            float* __restrict__ out_v, float* __restrict__ out_h)
{
    __shared__ __align__(16) char sm[4 * TILEB];
    const uint32_t sb = smem_u32(sm);
    GEMM_VARS();
    const int z = blockIdx.z, br = z >> 3, b = z & 7;
    const int bm = blockIdx.y * 128, bn = blockIdx.x * 128;
    const long long sX = (long long)C_ * N_;

    const bf16* gA = Wb + 262144 + br * 65536 + (long long)(bm + lrow) * MID_ + lhalf * 16;
    const bf16* gB = oTg + (long long)z * N_ * MID_ + (long long)(bn + lrow) * MID_ + lhalf * 16;
    GEMM_ADDRS(sb);
    PLAIN_LD_ST();
    GEMM_MAINLOOP(4, LD, ST);       // K = MID = 128

    const float* Bi = br ? bfah : bfav;
    float* Cb = (br ? out_h : out_v) + (long long)b * sX;
    const float* Rb = x + (long long)b * sX;
    #pragma unroll
    for (int t = 0; t < 2; ++t)
        #pragma unroll
        for (int j = 0; j < 8; ++j) {
            const int cc = bn + wn * 64 + j * 8 + tig * 2;
            #pragma unroll
            for (int h = 0; h < 2; ++h) {
                const int rr = bm + wm * 32 + t * 16 + gid + h * 8;
                float2 r2 = *(const float2*)(Rb + (long long)rr * N_ + cc);
                float v0 = d[t][j][h * 2]     + Bi[rr] + r2.x;
                float v1 = d[t][j][h * 2 + 1] + Bi[rr] + r2.y;
                *(float2*)(Cb + (long long)rr * N_ + cc) = make_float2(v0, v1);
            }
        }
}

// ---------------- small utility kernels ----------------------------------------
// g2 = g * (1/D) per contraction column
__global__ void __launch_bounds__(256)
scale_g(const bf16* __restrict__ gp, const float* __restrict__ D,
        bf16* __restrict__ g2)
{
    const long long i2 = (long long)blockIdx.x * 256 + threadIdx.x;  // bf162 units
    const int n2 = (int)(i2 % (N_ / 2));
    const int zb = (int)(i2 / ((long long)(N_ / 2) * MID_));          // br*8+b
    const float* Dp = D + zb * N_ + n2 * 2;
    float2 f = __bfloat1622float2(((const bf162*)gp)[i2]);
    f.x = f.x / Dp[0];
    f.y = f.y / Dp[1];
    ((bf162*)g2)[i2] = __floats2bfloat162_rn(f.x, f.y);
}

__global__ void __launch_bounds__(256)
transpose_k(const float* __restrict__ x, const float* __restrict__ xh,
            const float* __restrict__ xv, bf16* __restrict__ out)
{
    __shared__ float t[32][33];
    const int z = blockIdx.z;
    const int tsel = z / B_, b = z % B_;
    const float* src = (tsel == 0) ? x : (tsel == 1) ? xh : xv;
    src += (long long)b * C_ * N_;
    bf16* dst = out + (long long)z * N_ * C_;
    const int n0 = blockIdx.x * 32, c0 = blockIdx.y * 32;
    const int tx = threadIdx.x & 31, ty = threadIdx.x >> 5;
    #pragma unroll
    for (int k = 0; k < 4; ++k)
        t[ty + k * 8][tx] = src[(long long)(c0 + ty + k * 8) * N_ + n0 + tx];
    __syncthreads();
    #pragma unroll
    for (int k = 0; k < 4; ++k)
        dst[(long long)(n0 + ty + k * 8) * C_ + c0 + tx] =
            __float2bfloat16(t[tx][ty + k * 8]);
}

// converts weights; also zeroes D (first 2*B*N threads)
__global__ void __launch_bounds__(256)
conv_w(const float* w0, const float* w1, const float* w2,
       const float* w3, const float* w4, const float* w5,
       bf16* out, float* D)
{
    const int idx = blockIdx.x * 256 + threadIdx.x;
    if (idx < 2 * B_ * N_) D[idx] = 0.f;
    const int seg = idx >> 16, off = idx & 65535;
    const float* s = (seg == 0) ? w0 : (seg == 1) ? w1 : (seg == 2) ? w2
                   : (seg == 3) ? w3 : (seg == 4) ? w4 : w5;
    out[idx] = __float2bfloat16(s[off]);
}

// ---------------- launch --------------------------------------------------------
extern "C" void kernel_launch(void* const* d_in, const int* in_sizes, int n_in,
                              void* d_out, int out_size)
{
    (void)in_sizes; (void)n_in; (void)out_size;
    const float* x    = (const float*)d_in[0];
    const float* x_h  = (const float*)d_in[1];
    const float* x_v  = (const float*)d_in[2];
    const float* Wa   = (const float*)d_in[3];
    const float* ba   = (const float*)d_in[4];
    const float* ga   = (const float*)d_in[5];
    const float* ta   = (const float*)d_in[6];
    const float* Wv   = (const float*)d_in[7];
    const float* bv   = (const float*)d_in[8];
    const float* gv   = (const float*)d_in[9];
    const float* tv   = (const float*)d_in[10];
    const float* Wgav = (const float*)d_in[11];
    const float* bgav = (const float*)d_in[12];
    const float* Wgah = (const float*)d_in[13];
    const float* bgah = (const float*)d_in[14];
    const float* Wfav = (const float*)d_in[15];
    const float* bfav = (const float*)d_in[16];
    const float* Wfah = (const float*)d_in[17];
    const float* bfah = (const float*)d_in[18];

    bf16 *xT, *fT, *gp, *g2, *Lt, *oT, *Wb;
    float *Dv;
    cudaGetSymbolAddress((void**)&xT, g_xT);
    cudaGetSymbolAddress((void**)&fT, g_fT);
    cudaGetSymbolAddress((void**)&gp, g_gp);
    cudaGetSymbolAddress((void**)&g2, g_g2);
    cudaGetSymbolAddress((void**)&Lt, g_Lt);
    cudaGetSymbolAddress((void**)&oT, g_oT);
    cudaGetSymbolAddress((void**)&Dv, g_D);
    cudaGetSymbolAddress((void**)&Wb, g_Wb);

    float* out_h = (float*)d_out;
    float* out_v = (float*)d_out + (long long)B_ * C_ * N_;

    dim3 blk(256);
    conv_w<<<1536, blk>>>(Wa, Wv, Wgav, Wgah, Wfav, Wfah, Wb, Dv);
    transpose_k<<<dim3(N_/32, C_/32, 3 * B_), blk>>>(x, x_h, x_v, xT);

    // all 5 projections, one launch
    proj_all<<<dim3(N_/128, 1, 40), blk>>>(xT, Wb, fT, gp,
                                           ba, ga, ta, bv, gv, tv, bgav, bgah);

    // logits + D accumulation, both branches
    const long long segF = (long long)B_ * N_ * MID_;
    mma_logits<<<dim3(N_/128, N_/128, 16), blk>>>(fT, fT + segF, fT + 2 * segF,
                                                  Lt, Dv);

    // fold 1/D into g
    scale_g<<<(int)((2LL * B_ * MID_ * N_ / 2) / 256), blk>>>(gp, Dv, g2);

    // apply, both branches
    mma_apply<<<dim3(1, N_/128, 16), blk>>>(Lt, g2, oT);

    // output convs + residual, both branches
    outconv_all<<<dim3(N_/128, C_/128, 16), blk>>>(Wb, oT, x, bfav, bfah,
                                                   out_v, out_h);
}

// round 13
// speedup vs baseline: 4.4186x; 1.0390x over previous
#include <cuda_runtime.h>
#include <cuda_bf16.h>
#include <cstdint>
#include <math.h>

#define B_   8
#define C_   512
#define MID_ 128
#define N_   2304
#define SCALE_f 0.08838834764831845f

typedef __nv_bfloat16  bf16;
typedef __nv_bfloat162 bf162;

// ---------------- scratch (device globals) -------------------------------------
__device__ bf16  g_xT [3LL * B_ * N_ * C_];       // [t][b][n][c]  t:0=x 1=x_h 2=x_v
__device__ bf16  g_fT [3LL * B_ * N_ * MID_];     // [t][b][n][mid] 0=fa 1=fv 2=fh
__device__ bf16  g_gp [2LL * B_ * MID_ * N_];     // [t][b][mid][n] 0=gav 1=gah
__device__ bf16  g_g2 [2LL * B_ * MID_ * N_];     // g scaled by 1/D
__device__ bf16  g_Lt [2LL * B_ * N_ * N_];       // P[br][b][j][i] = exp(s*L[i][j])
__device__ bf16  g_oT [2LL * B_ * N_ * MID_];     // oT[br][b][j][m]
__device__ float g_D  [2 * B_ * N_];              // row denominators
__device__ bf16  g_Wb [6 * 65536];                // converted weights

// ---------------- helpers -------------------------------------------------------
__device__ __forceinline__ uint32_t smem_u32(const void* p) {
    uint32_t a;
    asm("{ .reg .u64 t; cvta.to.shared.u64 t, %1; cvt.u32.u64 %0, t; }" : "=r"(a) : "l"(p));
    return a;
}
// fast exp: 2^(x*log2e), FFMA-only
__device__ __forceinline__ float fexp(float x) {
    float y = x * 1.4426950408889634f;
    float j = rintf(y);
    float f = y - j;
    float p = 0.0013333558f;
    p = fmaf(p, f, 0.0096181291f);
    p = fmaf(p, f, 0.0555041087f);
    p = fmaf(p, f, 0.2402265070f);
    p = fmaf(p, f, 0.6931471806f);
    p = fmaf(p, f, 1.0f);
    return __int_as_float(__float_as_int(p) + (((int)j) << 23));
}

#define LDSM4(R, a)                                                           \
    asm volatile("ldmatrix.sync.aligned.m8n8.x4.shared.b16 {%0,%1,%2,%3}, [%4];" \
        : "=r"((R)[0]), "=r"((R)[1]), "=r"((R)[2]), "=r"((R)[3]) : "r"(a))

#define MMA16(D, A, b0, b1)                                                   \
    asm volatile("mma.sync.aligned.m16n8k16.row.col.f32.bf16.bf16.f32 "       \
        "{%0,%1,%2,%3},{%4,%5,%6,%7},{%8,%9},{%0,%1,%2,%3};"                  \
        : "+f"((D)[0]), "+f"((D)[1]), "+f"((D)[2]), "+f"((D)[3])              \
        : "r"((A)[0]), "r"((A)[1]), "r"((A)[2]), "r"((A)[3]), "r"(b0), "r"(b1))

#define STS128(a, v)                                                          \
    asm volatile("st.shared.v4.b32 [%0], {%1,%2,%3,%4};"                      \
        :: "r"(a), "r"((v).x), "r"((v).y), "r"((v).z), "r"((v).w) : "memory")

#define TILEB 10240   // A bufs at 0/10240, B bufs at 20480/30720; pitch 40 bf16

// ======= shared GEMM prologue/mainloop macros ===================================
#define GEMM_VARS()                                                           \
    const int tid = threadIdx.x, lane = tid & 31, wid = tid >> 5;             \
    const int wm = wid & 3, wn = wid >> 2, gid = lane >> 2, tig = lane & 3;   \
    const int lrow = tid >> 1, lhalf = tid & 1;                               \
    float d[2][8][4];                                                         \
    _Pragma("unroll")                                                         \
    for (int t = 0; t < 2; ++t)                                               \
        _Pragma("unroll")                                                     \
        for (int j = 0; j < 8; ++j)                                           \
            _Pragma("unroll")                                                 \
            for (int c = 0; c < 4; ++c) d[t][j][c] = 0.f;

#define GEMM_ADDRS(sb)                                                        \
    const uint32_t stA = (sb) + lrow * 80 + lhalf * 32;                       \
    const uint32_t stB = stA + 2 * TILEB;                                     \
    const uint32_t aAddr = (sb) + (wm * 32 + (lane & 15)) * 80 + (lane >> 4) * 16; \
    const uint32_t bAddr = (sb) + 2 * TILEB + (wn * 64 + (lane & 15)) * 80 + (lane >> 4) * 16;

#define GEMM_MAINLOOP(nch, LD, ST)                                            \
    LD(0); ST(0, 0);                                                          \
    for (int ch = 0; ch < (nch); ++ch) {                                      \
        __syncthreads();                                                      \
        if (ch + 1 < (nch)) LD((ch + 1) << 5);                                \
        const uint32_t ab = aAddr + (ch & 1) * TILEB;                         \
        const uint32_t bb = bAddr + (ch & 1) * TILEB;                         \
        _Pragma("unroll")                                                     \
        for (int kk = 0; kk < 2; ++kk) {                                      \
            uint32_t A0[4], A1[4], Bv[4][4];                                  \
            LDSM4(A0, ab + kk * 32);                                          \
            LDSM4(A1, ab + 1280 + kk * 32);                                   \
            _Pragma("unroll")                                                 \
            for (int jp = 0; jp < 4; ++jp) LDSM4(Bv[jp], bb + jp * 1280 + kk * 32); \
            _Pragma("unroll")                                                 \
            for (int j = 0; j < 8; ++j) {                                     \
                const int jp = j >> 1, o = j & 1;                             \
                MMA16(d[0][j], A0, Bv[jp][o], Bv[jp][o + 2]);                 \
                MMA16(d[1][j], A1, Bv[jp][o], Bv[jp][o + 2]);                 \
            }                                                                 \
        }                                                                     \
        if (ch + 1 < (nch)) ST((ch + 1) & 1, (ch + 1) << 5);                  \
    }

#define PLAIN_LD_ST()                                                         \
    uint4 ra0, ra1, rb0, rb1;                                                 \
    auto LD = [&](int k0) {                                                   \
        ra0 = *(const uint4*)(gA + k0);  ra1 = *(const uint4*)(gA + k0 + 8);  \
        rb0 = *(const uint4*)(gB + k0);  rb1 = *(const uint4*)(gB + k0 + 8);  \
    };                                                                        \
    auto ST = [&](int buf, int k0) {                                          \
        (void)k0;                                                             \
        uint32_t a = stA + buf * TILEB, b = stB + buf * TILEB;                \
        STS128(a, ra0); STS128(a + 16, ra1);                                  \
        STS128(b, rb0); STS128(b + 16, rb1);                                  \
    };

// ---- bf16 tile staging: swizzled SMEM word = rr*64 + ((cc2 + 4*rr) & 63) ------
__device__ __forceinline__ void sts_bf162(uint32_t sb, int rr, int cc2, bf162 v) {
    const int w = rr * 64 + ((cc2 + rr * 4) & 63);
    asm volatile("st.shared.b32 [%0], %1;"
                 :: "r"(sb + 4 * w), "r"(*(uint32_t*)&v) : "memory");
}
__device__ __forceinline__ void copy_tile_bf16(uint32_t sb, bf16* Cb, int ldc, int tid) {
    #pragma unroll
    for (int it = 0; it < 8; ++it) {
        const int q = it * 256 + tid;
        const int rr = q >> 4, k = q & 15;
        const int w = rr * 64 + (((k + rr) * 4) & 63);
        uint4 v;
        asm volatile("ld.shared.v4.b32 {%0,%1,%2,%3}, [%4];"
                     : "=r"(v.x), "=r"(v.y), "=r"(v.z), "=r"(v.w) : "r"(sb + 4 * w));
        *(uint4*)(Cb + (long long)rr * ldc + k * 8) = v;
    }
}

// ---------------- merged projections: 5 GEMMs x 8 batches in one launch --------
__global__ void __launch_bounds__(256, 2)
proj_all(const bf16* __restrict__ xT, const bf16* __restrict__ Wb,
         bf16* __restrict__ fT, bf16* __restrict__ gp,
         const float* __restrict__ ba, const float* __restrict__ ga, const float* __restrict__ ta,
         const float* __restrict__ bv, const float* __restrict__ gv, const float* __restrict__ tv,
         const float* __restrict__ bgav, const float* __restrict__ bgah)
{
    __shared__ __align__(16) char sm[4 * TILEB];
    const uint32_t sb = smem_u32(sm);
    GEMM_VARS();
    const int z = blockIdx.z, p = z >> 3, b = z & 7;
    const int bx = blockIdx.x;
    const long long sXb = (long long)N_ * C_;

    const bf16 *gA, *gB;
    int bm, bn;
    if (p < 3) {
        const int tsel = (p == 0) ? 0 : (p == 1 ? 2 : 1);
        bm = bx * 128; bn = 0;
        gA = xT + (long long)(tsel * B_ + b) * sXb + (long long)(bm + lrow) * C_ + lhalf * 16;
        gB = Wb + (p == 0 ? 0 : 65536) + lrow * C_ + lhalf * 16;
    } else {
        bm = 0; bn = bx * 128;
        gA = Wb + 131072 + (p - 3) * 65536 + lrow * C_ + lhalf * 16;
        gB = xT + (long long)b * sXb + (long long)(bn + lrow) * C_ + lhalf * 16;
    }
    GEMM_ADDRS(sb);
    PLAIN_LD_ST();
    GEMM_MAINLOOP(16, LD, ST);      // K = 512

    __syncthreads();
    const float rs = rsqrtf(1.f + 1e-5f);
    if (p < 3) {
        const float* Bi = (p == 0) ? ba : bv;
        const float* Ga = (p == 0) ? ga : gv;
        const float* Be = (p == 0) ? ta : tv;
        #pragma unroll
        for (int t = 0; t < 2; ++t)
            #pragma unroll
            for (int j = 0; j < 8; ++j) {
                const int cc = wn * 64 + j * 8 + tig * 2;
                const float b0 = Bi[cc],      b1 = Bi[cc + 1];
                const float s0 = Ga[cc] * rs, s1 = Ga[cc + 1] * rs;
                const float e0 = Be[cc],      e1 = Be[cc + 1];
                #pragma unroll
                for (int h = 0; h < 2; ++h) {
                    const int rr = wm * 32 + t * 16 + gid + h * 8;
                    float v0 = fmaxf(fmaf(d[t][j][h * 2]     + b0, s0, e0), 0.f);
                    float v1 = fmaxf(fmaf(d[t][j][h * 2 + 1] + b1, s1, e1), 0.f);
                    sts_bf162(sb, rr, cc >> 1, __floats2bfloat162_rn(v0, v1));
                }
            }
        __syncthreads();
        bf16* Cb = fT + (long long)(p * B_ + b) * ((long long)N_ * MID_) + (long long)bm * MID_;
        copy_tile_bf16(sb, Cb, MID_, tid);
    } else {
        const float* Bi = (p == 3) ? bgav : bgah;
        #pragma unroll
        for (int t = 0; t < 2; ++t)
            #pragma unroll
            for (int j = 0; j < 8; ++j) {
                const int cc = wn * 64 + j * 8 + tig * 2;
                #pragma unroll
                for (int h = 0; h < 2; ++h) {
                    const int rr = wm * 32 + t * 16 + gid + h * 8;
                    float v0 = d[t][j][h * 2]     + Bi[rr];
                    float v1 = d[t][j][h * 2 + 1] + Bi[rr];
                    sts_bf162(sb, rr, cc >> 1, __floats2bfloat162_rn(v0, v1));
                }
            }
        __syncthreads();
        bf16* Cb = gp + (long long)((p - 3) * B_ + b) * ((long long)MID_ * N_) + bn;
        copy_tile_bf16(sb, Cb, N_, tid);
    }
}

// -------- logits (both branches): P = exp(s*L^T) bf16; D[i] += col sums --------
__global__ void __launch_bounds__(256, 2)
mma_logits(const bf16* __restrict__ faT, const bf16* __restrict__ fvT,
           const bf16* __restrict__ fhT, bf16* __restrict__ Pout,
           float* __restrict__ Dv)
{
    __shared__ __align__(16) char sm[4 * TILEB];
    const uint32_t sb = smem_u32(sm);
    GEMM_VARS();
    const int z = blockIdx.z, br = z >> 3, b = z & 7;
    const int bm = blockIdx.y * 128, bn = blockIdx.x * 128;
    const long long sF = (long long)N_ * MID_;

    const bf16* fq = br ? fhT : fvT;
    const bf16* gA = faT + (long long)b * sF + (long long)(bm + lrow) * MID_ + lhalf * 16;
    const bf16* gB = fq  + (long long)b * sF + (long long)(bn + lrow) * MID_ + lhalf * 16;
    GEMM_ADDRS(sb);
    PLAIN_LD_ST();
    GEMM_MAINLOOP(4, LD, ST);       // K = MID = 128

    __syncthreads();
    float* Dp = Dv + z * N_;
    #pragma unroll
    for (int j = 0; j < 8; ++j) {
        const int cc = bn + wn * 64 + j * 8 + tig * 2;
        float s0 = 0.f, s1 = 0.f;
        #pragma unroll
        for (int t = 0; t < 2; ++t)
            #pragma unroll
            for (int h = 0; h < 2; ++h) {
                const int rr = wm * 32 + t * 16 + gid + h * 8;
                float e0 = fexp(SCALE_f * d[t][j][h * 2]);
                float e1 = fexp(SCALE_f * d[t][j][h * 2 + 1]);
                bf162 r = __floats2bfloat162_rn(e0, e1);
                sts_bf162(sb, rr, (cc - bn) >> 1, r);
                float2 f = __bfloat1622float2(r);   // sum the ROUNDED values
                s0 += f.x; s1 += f.y;
            }
        s0 += __shfl_xor_sync(0xffffffffu, s0, 4);
        s0 += __shfl_xor_sync(0xffffffffu, s0, 8);
        s0 += __shfl_xor_sync(0xffffffffu, s0, 16);
        s1 += __shfl_xor_sync(0xffffffffu, s1, 4);
        s1 += __shfl_xor_sync(0xffffffffu, s1, 8);
        s1 += __shfl_xor_sync(0xffffffffu, s1, 16);
        if (gid == 0) {
            atomicAdd(Dp + cc,     s0);
            atomicAdd(Dp + cc + 1, s1);
        }
    }
    __syncthreads();
    bf16* Cb = Pout + (long long)z * N_ * N_ + (long long)bm * N_ + bn;
    copy_tile_bf16(sb, Cb, N_, tid);
}

// -------- apply (both branches): oT = P x g2^T (plain GEMM, z=16) --------------
__global__ void __launch_bounds__(256, 2)
mma_apply(const bf16* __restrict__ Pg, const bf16* __restrict__ g2,
          bf16* __restrict__ oTg)
{
    __shared__ __align__(16) char sm[4 * TILEB];
    const uint32_t sb = smem_u32(sm);
    GEMM_VARS();
    const int z = blockIdx.z;
    const int bm = blockIdx.y * 128;

    const bf16* gA = Pg + (long long)z * N_ * N_ + (long long)(bm + lrow) * N_ + lhalf * 16;
    const bf16* gB = g2 + (long long)z * MID_ * N_ + (long long)lrow * N_ + lhalf * 16;
    GEMM_ADDRS(sb);
    PLAIN_LD_ST();
    GEMM_MAINLOOP(N_ / 32, LD, ST); // 72 chunks

    __syncthreads();
    #pragma unroll
    for (int t = 0; t < 2; ++t)
        #pragma unroll
        for (int j = 0; j < 8; ++j) {
            const int cc = wn * 64 + j * 8 + tig * 2;
            #pragma unroll
            for (int h = 0; h < 2; ++h) {
                const int rr = wm * 32 + t * 16 + gid + h * 8;
                sts_bf162(sb, rr, cc >> 1,
                          __floats2bfloat162_rn(d[t][j][h * 2], d[t][j][h * 2 + 1]));
            }
        }
    __syncthreads();
    bf16* Cb = oTg + (long long)z * N_ * MID_ + (long long)bm * MID_;
    copy_tile_bf16(sb, Cb, MID_, tid);
}

// -------- merged output convs: out = Wf x oT^T + bias + x (z=16) ---------------
__global__ void __launch_bounds__(256, 2)
outconv_all(const bf16* __restrict__ Wb, const bf16* __restrict__ oTg,
            const float* __restrict__ x,
            const float* __restrict__ bfav, const float* __restrict__ bfah,
            float* __restrict__ out_v, float* __restrict__ out_h)
{
    __shared__ __align__(16) char sm[4 * TILEB];
    const uint32_t sb = smem_u32(sm);
    GEMM_VARS();
    const int z = blockIdx.z, br = z >> 3, b = z & 7;
    const int bm = blockIdx.y * 128, bn = blockIdx.x * 128;
    const long long sX = (long long)C_ * N_;

    const bf16* gA = Wb + 262144 + br * 65536 + (long long)(bm + lrow) * MID_ + lhalf * 16;
    const bf16* gB = oTg + (long long)z * N_ * MID_ + (long long)(bn + lrow) * MID_ + lhalf * 16;
    GEMM_ADDRS(sb);
    PLAIN_LD_ST();
    GEMM_MAINLOOP(4, LD, ST);       // K = MID = 128

    const float* Bi = br ? bfah : bfav;
    float* Cb = (br ? out_h : out_v) + (long long)b * sX;
    const float* Rb = x + (long long)b * sX;

    // two passes of 64 rows each (32 KB fp32 staging), swizzle word = s*128 + ((cc+4s)&127)
    #pragma unroll
    for (int t = 0; t < 2; ++t) {
        __syncthreads();
        #pragma unroll
        for (int j = 0; j < 8; ++j) {
            const int cc = wn * 64 + j * 8 + tig * 2;
            #pragma unroll
            for (int h = 0; h < 2; ++h) {
                const int srow = wm * 16 + gid + h * 8;   // 0..63
                const int w = srow * 128 + ((cc + srow * 4) & 127);
                asm volatile("st.shared.v2.b32 [%0], {%1,%2};"
                             :: "r"(sb + 4 * w),
                                "r"(__float_as_uint(d[t][j][h * 2])),
                                "r"(__float_as_uint(d[t][j][h * 2 + 1])) : "memory");
            }
        }
        __syncthreads();
        #pragma unroll
        for (int it = 0; it < 8; ++it) {
            const int q = it * 256 + tid;
            const int srow = q >> 5, k = q & 31;          // 32 float4 per row
            const int w = srow * 128 + (((k + srow) * 4) & 127);
            float4 v;
            asm volatile("ld.shared.v4.b32 {%0,%1,%2,%3}, [%4];"
                         : "=f"(v.x), "=f"(v.y), "=f"(v.z), "=f"(v.w) : "r"(sb + 4 * w));
            const int rr = bm + (srow >> 4) * 32 + t * 16 + (srow & 15);
            const long long off = (long long)rr * N_ + bn + k * 4;
            float4 r4 = *(const float4*)(Rb + off);
            const float bi = Bi[rr];
            v.x += bi + r4.x; v.y += bi + r4.y; v.z += bi + r4.z; v.w += bi + r4.w;
            *(float4*)(Cb + off) = v;
        }
    }
}

// ---------------- small utility kernels ----------------------------------------
__global__ void __launch_bounds__(256)
scale_g(const bf16* __restrict__ gp, const float* __restrict__ D,
        bf16* __restrict__ g2)
{
    const long long i2 = (long long)blockIdx.x * 256 + threadIdx.x;  // bf162 units
    const int n2 = (int)(i2 % (N_ / 2));
    const int zb = (int)(i2 / ((long long)(N_ / 2) * MID_));          // br*8+b
    const float* Dp = D + zb * N_ + n2 * 2;
    float2 f = __bfloat1622float2(((const bf162*)gp)[i2]);
    f.x = f.x / Dp[0];
    f.y = f.y / Dp[1];
    ((bf162*)g2)[i2] = __floats2bfloat162_rn(f.x, f.y);
}

__global__ void __launch_bounds__(256)
transpose_k(const float* __restrict__ x, const float* __restrict__ xh,
            const float* __restrict__ xv, bf16* __restrict__ out)
{
    __shared__ float t[32][33];
    const int z = blockIdx.z;
    const int tsel = z / B_, b = z % B_;
    const float* src = (tsel == 0) ? x : (tsel == 1) ? xh : xv;
    src += (long long)b * C_ * N_;
    bf16* dst = out + (long long)z * N_ * C_;
    const int n0 = blockIdx.x * 32, c0 = blockIdx.y * 32;
    const int tx = threadIdx.x & 31, ty = threadIdx.x >> 5;
    #pragma unroll
    for (int k = 0; k < 4; ++k)
        t[ty + k * 8][tx] = src[(long long)(c0 + ty + k * 8) * N_ + n0 + tx];
    __syncthreads();
    #pragma unroll
    for (int k = 0; k < 4; ++k)
        dst[(long long)(n0 + ty + k * 8) * C_ + c0 + tx] =
            __float2bfloat16(t[tx][ty + k * 8]);
}

__global__ void __launch_bounds__(256)
conv_w(const float* w0, const float* w1, const float* w2,
       const float* w3, const float* w4, const float* w5,
       bf16* out, float* D)
{
    const int idx = blockIdx.x * 256 + threadIdx.x;
    if (idx < 2 * B_ * N_) D[idx] = 0.f;
    const int seg = idx >> 16, off = idx & 65535;
    const float* s = (seg == 0) ? w0 : (seg == 1) ? w1 : (seg == 2) ? w2
                   : (seg == 3) ? w3 : (seg == 4) ? w4 : w5;
    out[idx] = __float2bfloat16(s[off]);
}

// ---------------- launch --------------------------------------------------------
extern "C" void kernel_launch(void* const* d_in, const int* in_sizes, int n_in,
                              void* d_out, int out_size)
{
    (void)in_sizes; (void)n_in; (void)out_size;
    const float* x    = (const float*)d_in[0];
    const float* x_h  = (const float*)d_in[1];
    const float* x_v  = (const float*)d_in[2];
    const float* Wa   = (const float*)d_in[3];
    const float* ba   = (const float*)d_in[4];
    const float* ga   = (const float*)d_in[5];
    const float* ta   = (const float*)d_in[6];
    const float* Wv   = (const float*)d_in[7];
    const float* bv   = (const float*)d_in[8];
    const float* gv   = (const float*)d_in[9];
    const float* tv   = (const float*)d_in[10];
    const float* Wgav = (const float*)d_in[11];
    const float* bgav = (const float*)d_in[12];
    const float* Wgah = (const float*)d_in[13];
    const float* bgah = (const float*)d_in[14];
    const float* Wfav = (const float*)d_in[15];
    const float* bfav = (const float*)d_in[16];
    const float* Wfah = (const float*)d_in[17];
    const float* bfah = (const float*)d_in[18];

    bf16 *xT, *fT, *gp, *g2, *Lt, *oT, *Wb;
    float *Dv;
    cudaGetSymbolAddress((void**)&xT, g_xT);
    cudaGetSymbolAddress((void**)&fT, g_fT);
    cudaGetSymbolAddress((void**)&gp, g_gp);
    cudaGetSymbolAddress((void**)&g2, g_g2);
    cudaGetSymbolAddress((void**)&Lt, g_Lt);
    cudaGetSymbolAddress((void**)&oT, g_oT);
    cudaGetSymbolAddress((void**)&Dv, g_D);
    cudaGetSymbolAddress((void**)&Wb, g_Wb);

    float* out_h = (float*)d_out;
    float* out_v = (float*)d_out + (long long)B_ * C_ * N_;

    dim3 blk(256);
    conv_w<<<1536, blk>>>(Wa, Wv, Wgav, Wgah, Wfav, Wfah, Wb, Dv);
    transpose_k<<<dim3(N_/32, C_/32, 3 * B_), blk>>>(x, x_h, x_v, xT);

    // all 5 projections, one launch
    proj_all<<<dim3(N_/128, 1, 40), blk>>>(xT, Wb, fT, gp,
                                           ba, ga, ta, bv, gv, tv, bgav, bgah);

    // logits + D accumulation, both branches
    const long long segF = (long long)B_ * N_ * MID_;
    mma_logits<<<dim3(N_/128, N_/128, 16), blk>>>(fT, fT + segF, fT + 2 * segF,
                                                  Lt, Dv);

    // fold 1/D into g
    scale_g<<<(int)((2LL * B_ * MID_ * N_ / 2) / 256), blk>>>(gp, Dv, g2);

    // apply, both branches
    mma_apply<<<dim3(1, N_/128, 16), blk>>>(Lt, g2, oT);

    // output convs + residual, both branches
    outconv_all<<<dim3(N_/128, C_/128, 16), blk>>>(Wb, oT, x, bfav, bfah,
                                                   out_v, out_h);
}

// round 14
// speedup vs baseline: 4.9868x; 1.1286x over previous
#include <cuda_runtime.h>
#include <cuda_bf16.h>
#include <cstdint>
#include <math.h>

#define B_   8
#define C_   512
#define MID_ 128
#define N_   2304
#define SCALE_f 0.08838834764831845f
#define K2E_f  0.12751884810630747f   // SCALE * log2(e)

typedef __nv_bfloat16  bf16;
typedef __nv_bfloat162 bf162;

// ---------------- scratch (device globals) -------------------------------------
__device__ bf16  g_xT [3LL * B_ * N_ * C_];       // [t][b][n][c]  t:0=x 1=x_h 2=x_v
__device__ bf16  g_fT [3LL * B_ * N_ * MID_];     // [t][b][n][mid] 0=fa 1=fv 2=fh
__device__ bf16  g_gp [2LL * B_ * MID_ * N_];     // [t][b][mid][n] 0=gav 1=gah
__device__ bf16  g_g2 [2LL * B_ * MID_ * N_];     // g scaled by 1/D
__device__ bf16  g_Lt [2LL * B_ * N_ * N_];       // P[br][b][j][i] = exp(s*L[i][j])
__device__ bf16  g_oT [2LL * B_ * N_ * MID_];     // oT[br][b][j][m]
__device__ float g_D  [2 * B_ * N_];              // row denominators
__device__ bf16  g_Wb [6 * 65536];                // converted weights

// ---------------- helpers -------------------------------------------------------
__device__ __forceinline__ uint32_t smem_u32(const void* p) {
    uint32_t a;
    asm("{ .reg .u64 t; cvta.to.shared.u64 t, %1; cvt.u32.u64 %0, t; }" : "=r"(a) : "l"(p));
    return a;
}
__device__ __forceinline__ float ex2f(float x) {   // 2^x, MUFU
    float r;
    asm("ex2.approx.f32 %0, %1;" : "=f"(r) : "f"(x));
    return r;
}

#define LDSM4(R, a)                                                           \
    asm volatile("ldmatrix.sync.aligned.m8n8.x4.shared.b16 {%0,%1,%2,%3}, [%4];" \
        : "=r"((R)[0]), "=r"((R)[1]), "=r"((R)[2]), "=r"((R)[3]) : "r"(a))

#define MMA16(D, A, b0, b1)                                                   \
    asm volatile("mma.sync.aligned.m16n8k16.row.col.f32.bf16.bf16.f32 "       \
        "{%0,%1,%2,%3},{%4,%5,%6,%7},{%8,%9},{%0,%1,%2,%3};"                  \
        : "+f"((D)[0]), "+f"((D)[1]), "+f"((D)[2]), "+f"((D)[3])              \
        : "r"((A)[0]), "r"((A)[1]), "r"((A)[2]), "r"((A)[3]), "r"(b0), "r"(b1))

#define CP16(dst, src)                                                        \
    asm volatile("cp.async.cg.shared.global [%0], [%1], 16;"                  \
        :: "r"(dst), "l"(src) : "memory")

// stage block = 20480 B: A tile [0,10240), B tile [10240,20480); pitch 80 B/row
#define STAGEB 20480
#define SMEM_SZ (3 * STAGEB)

// ======= shared GEMM prologue/mainloop macros ===================================
#define GEMM_VARS()                                                           \
    const int tid = threadIdx.x, lane = tid & 31, wid = tid >> 5;             \
    const int wm = wid & 3, wn = wid >> 2, gid = lane >> 2, tig = lane & 3;   \
    const int lrow = tid >> 1, lhalf = tid & 1;                               \
    float d[2][8][4];                                                         \
    _Pragma("unroll")                                                         \
    for (int t = 0; t < 2; ++t)                                               \
        _Pragma("unroll")                                                     \
        for (int j = 0; j < 8; ++j)                                           \
            _Pragma("unroll")                                                 \
            for (int c = 0; c < 4; ++c) d[t][j][c] = 0.f;

#define GEMM_ADDRS(sb)                                                        \
    const uint32_t stA = (sb) + lrow * 80 + lhalf * 32;                       \
    const uint32_t stB = stA + 10240;                                         \
    const uint32_t aAddr = (sb) + (wm * 32 + (lane & 15)) * 80 + (lane >> 4) * 16; \
    const uint32_t bAddr = (sb) + 10240 + (wn * 64 + (lane & 15)) * 80 + (lane >> 4) * 16;

// 3-stage cp.async pipeline mainloop. Needs gA, gB, stA, stB, aAddr, bAddr.
#define PIPE_MAINLOOP(nch)                                                    \
{                                                                             \
    const bf16 *pa = gA, *pb = gB;                                            \
    uint32_t io = 0;                                                          \
    auto ISSUE = [&](bool valid) {                                            \
        if (valid) {                                                          \
            CP16(stA + io, pa); CP16(stA + io + 16, pa + 8);                  \
            CP16(stB + io, pb); CP16(stB + io + 16, pb + 8);                  \
            pa += 32; pb += 32;                                               \
        }                                                                     \
        asm volatile("cp.async.commit_group;" ::: "memory");                  \
        io += STAGEB; if (io == SMEM_SZ) io = 0;                              \
    };                                                                        \
    ISSUE(true); ISSUE(1 < (nch));                                            \
    uint32_t co = 0;                                                          \
    for (int ch = 0; ch < (nch); ++ch) {                                      \
        asm volatile("cp.async.wait_group 1;" ::: "memory");                  \
        __syncthreads();                                                      \
        ISSUE(ch + 2 < (nch));                                                \
        const uint32_t ab = aAddr + co, bb = bAddr + co;                      \
        co += STAGEB; if (co == SMEM_SZ) co = 0;                              \
        _Pragma("unroll")                                                     \
        for (int kk = 0; kk < 2; ++kk) {                                      \
            uint32_t A0[4], A1[4], Bv[4][4];                                  \
            LDSM4(A0, ab + kk * 32);                                          \
            LDSM4(A1, ab + 1280 + kk * 32);                                   \
            _Pragma("unroll")                                                 \
            for (int jp = 0; jp < 4; ++jp) LDSM4(Bv[jp], bb + jp * 1280 + kk * 32); \
            _Pragma("unroll")                                                 \
            for (int j = 0; j < 8; ++j) {                                     \
                const int jp = j >> 1, o = j & 1;                             \
                MMA16(d[0][j], A0, Bv[jp][o], Bv[jp][o + 2]);                 \
                MMA16(d[1][j], A1, Bv[jp][o], Bv[jp][o + 2]);                 \
            }                                                                 \
        }                                                                     \
    }                                                                         \
}

// ---- bf16 tile staging: swizzled SMEM word = rr*64 + ((cc2 + 4*rr) & 63) ------
__device__ __forceinline__ void sts_bf162(uint32_t sb, int rr, int cc2, bf162 v) {
    const int w = rr * 64 + ((cc2 + rr * 4) & 63);
    asm volatile("st.shared.b32 [%0], %1;"
                 :: "r"(sb + 4 * w), "r"(*(uint32_t*)&v) : "memory");
}
__device__ __forceinline__ void copy_tile_bf16(uint32_t sb, bf16* Cb, int ldc, int tid) {
    #pragma unroll
    for (int it = 0; it < 8; ++it) {
        const int q = it * 256 + tid;
        const int rr = q >> 4, k = q & 15;
        const int w = rr * 64 + (((k + rr) * 4) & 63);
        uint4 v;
        asm volatile("ld.shared.v4.b32 {%0,%1,%2,%3}, [%4];"
                     : "=r"(v.x), "=r"(v.y), "=r"(v.z), "=r"(v.w) : "r"(sb + 4 * w));
        *(uint4*)(Cb + (long long)rr * ldc + k * 8) = v;
    }
}

// ---------------- merged projections: 5 GEMMs x 8 batches in one launch --------
__global__ void __launch_bounds__(256, 2)
proj_all(const bf16* __restrict__ xT, const bf16* __restrict__ Wb,
         bf16* __restrict__ fT, bf16* __restrict__ gp,
         const float* __restrict__ ba, const float* __restrict__ ga, const float* __restrict__ ta,
         const float* __restrict__ bv, const float* __restrict__ gv, const float* __restrict__ tv,
         const float* __restrict__ bgav, const float* __restrict__ bgah)
{
    extern __shared__ __align__(16) char sm[];
    const uint32_t sb = smem_u32(sm);
    GEMM_VARS();
    const int z = blockIdx.z, p = z >> 3, b = z & 7;
    const int bx = blockIdx.x;
    const long long sXb = (long long)N_ * C_;

    const bf16 *gA, *gB;
    int bm, bn;
    if (p < 3) {
        const int tsel = (p == 0) ? 0 : (p == 1 ? 2 : 1);
        bm = bx * 128; bn = 0;
        gA = xT + (long long)(tsel * B_ + b) * sXb + (long long)(bm + lrow) * C_ + lhalf * 16;
        gB = Wb + (p == 0 ? 0 : 65536) + lrow * C_ + lhalf * 16;
    } else {
        bm = 0; bn = bx * 128;
        gA = Wb + 131072 + (p - 3) * 65536 + lrow * C_ + lhalf * 16;
        gB = xT + (long long)b * sXb + (long long)(bn + lrow) * C_ + lhalf * 16;
    }
    GEMM_ADDRS(sb);
    PIPE_MAINLOOP(16);              // K = 512

    __syncthreads();
    const float rs = rsqrtf(1.f + 1e-5f);
    if (p < 3) {
        const float* Bi = (p == 0) ? ba : bv;
        const float* Ga = (p == 0) ? ga : gv;
        const float* Be = (p == 0) ? ta : tv;
        #pragma unroll
        for (int t = 0; t < 2; ++t)
            #pragma unroll
            for (int j = 0; j < 8; ++j) {
                const int cc = wn * 64 + j * 8 + tig * 2;
                const float b0 = Bi[cc],      b1 = Bi[cc + 1];
                const float s0 = Ga[cc] * rs, s1 = Ga[cc + 1] * rs;
                const float e0 = Be[cc],      e1 = Be[cc + 1];
                #pragma unroll
                for (int h = 0; h < 2; ++h) {
                    const int rr = wm * 32 + t * 16 + gid + h * 8;
                    float v0 = fmaxf(fmaf(d[t][j][h * 2]     + b0, s0, e0), 0.f);
                    float v1 = fmaxf(fmaf(d[t][j][h * 2 + 1] + b1, s1, e1), 0.f);
                    sts_bf162(sb, rr, cc >> 1, __floats2bfloat162_rn(v0, v1));
                }
            }
        __syncthreads();
        bf16* Cb = fT + (long long)(p * B_ + b) * ((long long)N_ * MID_) + (long long)bm * MID_;
        copy_tile_bf16(sb, Cb, MID_, tid);
    } else {
        const float* Bi = (p == 3) ? bgav : bgah;
        #pragma unroll
        for (int t = 0; t < 2; ++t)
            #pragma unroll
            for (int j = 0; j < 8; ++j) {
                const int cc = wn * 64 + j * 8 + tig * 2;
                #pragma unroll
                for (int h = 0; h < 2; ++h) {
                    const int rr = wm * 32 + t * 16 + gid + h * 8;
                    float v0 = d[t][j][h * 2]     + Bi[rr];
                    float v1 = d[t][j][h * 2 + 1] + Bi[rr];
                    sts_bf162(sb, rr, cc >> 1, __floats2bfloat162_rn(v0, v1));
                }
            }
        __syncthreads();
        bf16* Cb = gp + (long long)((p - 3) * B_ + b) * ((long long)MID_ * N_) + bn;
        copy_tile_bf16(sb, Cb, N_, tid);
    }
}

// -------- logits (both branches): P = exp(s*L^T) bf16; D[i] += col sums --------
__global__ void __launch_bounds__(256, 2)
mma_logits(const bf16* __restrict__ faT, const bf16* __restrict__ fvT,
           const bf16* __restrict__ fhT, bf16* __restrict__ Pout,
           float* __restrict__ Dv)
{
    extern __shared__ __align__(16) char sm[];
    const uint32_t sb = smem_u32(sm);
    GEMM_VARS();
    const int z = blockIdx.z, br = z >> 3, b = z & 7;
    const int bm = blockIdx.y * 128, bn = blockIdx.x * 128;
    const long long sF = (long long)N_ * MID_;

    const bf16* fq = br ? fhT : fvT;
    const bf16* gA = faT + (long long)b * sF + (long long)(bm + lrow) * MID_ + lhalf * 16;
    const bf16* gB = fq  + (long long)b * sF + (long long)(bn + lrow) * MID_ + lhalf * 16;
    GEMM_ADDRS(sb);
    PIPE_MAINLOOP(4);               // K = MID = 128

    __syncthreads();
    float* Dp = Dv + z * N_;
    #pragma unroll
    for (int j = 0; j < 8; ++j) {
        const int cc = bn + wn * 64 + j * 8 + tig * 2;
        float s0 = 0.f, s1 = 0.f;
        #pragma unroll
        for (int t = 0; t < 2; ++t)
            #pragma unroll
            for (int h = 0; h < 2; ++h) {
                const int rr = wm * 32 + t * 16 + gid + h * 8;
                float e0 = ex2f(K2E_f * d[t][j][h * 2]);
                float e1 = ex2f(K2E_f * d[t][j][h * 2 + 1]);
                bf162 r = __floats2bfloat162_rn(e0, e1);
                sts_bf162(sb, rr, (cc - bn) >> 1, r);
                float2 f = __bfloat1622float2(r);   // sum the ROUNDED values
                s0 += f.x; s1 += f.y;
            }
        s0 += __shfl_xor_sync(0xffffffffu, s0, 4);
        s0 += __shfl_xor_sync(0xffffffffu, s0, 8);
        s0 += __shfl_xor_sync(0xffffffffu, s0, 16);
        s1 += __shfl_xor_sync(0xffffffffu, s1, 4);
        s1 += __shfl_xor_sync(0xffffffffu, s1, 8);
        s1 += __shfl_xor_sync(0xffffffffu, s1, 16);
        if (gid == 0) {
            atomicAdd(Dp + cc,     s0);
            atomicAdd(Dp + cc + 1, s1);
        }
    }
    __syncthreads();
    bf16* Cb = Pout + (long long)z * N_ * N_ + (long long)bm * N_ + bn;
    copy_tile_bf16(sb, Cb, N_, tid);
}

// -------- apply (both branches): oT = P x g2^T (plain GEMM, z=16) --------------
__global__ void __launch_bounds__(256, 2)
mma_apply(const bf16* __restrict__ Pg, const bf16* __restrict__ g2,
          bf16* __restrict__ oTg)
{
    extern __shared__ __align__(16) char sm[];
    const uint32_t sb = smem_u32(sm);
    GEMM_VARS();
    const int z = blockIdx.z;
    const int bm = blockIdx.y * 128;

    const bf16* gA = Pg + (long long)z * N_ * N_ + (long long)(bm + lrow) * N_ + lhalf * 16;
    const bf16* gB = g2 + (long long)z * MID_ * N_ + (long long)lrow * N_ + lhalf * 16;
    GEMM_ADDRS(sb);
    PIPE_MAINLOOP(N_ / 32);         // 72 chunks

    __syncthreads();
    #pragma unroll
    for (int t = 0; t < 2; ++t)
        #pragma unroll
        for (int j = 0; j < 8; ++j) {
            const int cc = wn * 64 + j * 8 + tig * 2;
            #pragma unroll
            for (int h = 0; h < 2; ++h) {
                const int rr = wm * 32 + t * 16 + gid + h * 8;
                sts_bf162(sb, rr, cc >> 1,
                          __floats2bfloat162_rn(d[t][j][h * 2], d[t][j][h * 2 + 1]));
            }
        }
    __syncthreads();
    bf16* Cb = oTg + (long long)z * N_ * MID_ + (long long)bm * MID_;
    copy_tile_bf16(sb, Cb, MID_, tid);
}

// -------- merged output convs: out = Wf x oT^T + bias + x (z=16) ---------------
__global__ void __launch_bounds__(256, 2)
outconv_all(const bf16* __restrict__ Wb, const bf16* __restrict__ oTg,
            const float* __restrict__ x,
            const float* __restrict__ bfav, const float* __restrict__ bfah,
            float* __restrict__ out_v, float* __restrict__ out_h)
{
    extern __shared__ __align__(16) char sm[];
    const uint32_t sb = smem_u32(sm);
    GEMM_VARS();
    const int z = blockIdx.z, br = z >> 3, b = z & 7;
    const int bm = blockIdx.y * 128, bn = blockIdx.x * 128;
    const long long sX = (long long)C_ * N_;

    const bf16* gA = Wb + 262144 + br * 65536 + (long long)(bm + lrow) * MID_ + lhalf * 16;
    const bf16* gB = oTg + (long long)z * N_ * MID_ + (long long)(bn + lrow) * MID_ + lhalf * 16;
    GEMM_ADDRS(sb);
    PIPE_MAINLOOP(4);               // K = MID = 128

    const float* Bi = br ? bfah : bfav;
    float* Cb = (br ? out_h : out_v) + (long long)b * sX;
    const float* Rb = x + (long long)b * sX;

    // two passes of 64 rows (32 KB fp32 staging), swizzle word = s*128 + ((cc+4s)&127)
    #pragma unroll
    for (int t = 0; t < 2; ++t) {
        __syncthreads();
        #pragma unroll
        for (int j = 0; j < 8; ++j) {
            const int cc = wn * 64 + j * 8 + tig * 2;
            #pragma unroll
            for (int h = 0; h < 2; ++h) {
                const int srow = wm * 16 + gid + h * 8;   // 0..63
                const int w = srow * 128 + ((cc + srow * 4) & 127);
                asm volatile("st.shared.v2.b32 [%0], {%1,%2};"
                             :: "r"(sb + 4 * w),
                                "r"(__float_as_uint(d[t][j][h * 2])),
                                "r"(__float_as_uint(d[t][j][h * 2 + 1])) : "memory");
            }
        }
        __syncthreads();
        #pragma unroll
        for (int it = 0; it < 8; ++it) {
            const int q = it * 256 + tid;
            const int srow = q >> 5, k = q & 31;          // 32 float4 per row
            const int w = srow * 128 + (((k + srow) * 4) & 127);
            float4 v;
            asm volatile("ld.shared.v4.b32 {%0,%1,%2,%3}, [%4];"
                         : "=f"(v.x), "=f"(v.y), "=f"(v.z), "=f"(v.w) : "r"(sb + 4 * w));
            const int rr = bm + (srow >> 4) * 32 + t * 16 + (srow & 15);
            const long long off = (long long)rr * N_ + bn + k * 4;
            float4 r4 = *(const float4*)(Rb + off);
            const float bi = Bi[rr];
            v.x += bi + r4.x; v.y += bi + r4.y; v.z += bi + r4.z; v.w += bi + r4.w;
            *(float4*)(Cb + off) = v;
        }
    }
}

// ---------------- small utility kernels ----------------------------------------
__global__ void __launch_bounds__(256)
scale_g(const bf16* __restrict__ gp, const float* __restrict__ D,
        bf16* __restrict__ g2)
{
    const long long i2 = (long long)blockIdx.x * 256 + threadIdx.x;  // bf162 units
    const int n2 = (int)(i2 % (N_ / 2));
    const int zb = (int)(i2 / ((long long)(N_ / 2) * MID_));          // br*8+b
    const float* Dp = D + zb * N_ + n2 * 2;
    float2 f = __bfloat1622float2(((const bf162*)gp)[i2]);
    f.x = f.x / Dp[0];
    f.y = f.y / Dp[1];
    ((bf162*)g2)[i2] = __floats2bfloat162_rn(f.x, f.y);
}

__global__ void __launch_bounds__(256)
transpose_k(const float* __restrict__ x, const float* __restrict__ xh,
            const float* __restrict__ xv, bf16* __restrict__ out)
{
    __shared__ float t[32][33];
    const int z = blockIdx.z;
    const int tsel = z / B_, b = z % B_;
    const float* src = (tsel == 0) ? x : (tsel == 1) ? xh : xv;
    src += (long long)b * C_ * N_;
    bf16* dst = out + (long long)z * N_ * C_;
    const int n0 = blockIdx.x * 32, c0 = blockIdx.y * 32;
    const int tx = threadIdx.x & 31, ty = threadIdx.x >> 5;
    #pragma unroll
    for (int k = 0; k < 4; ++k)
        t[ty + k * 8][tx] = src[(long long)(c0 + ty + k * 8) * N_ + n0 + tx];
    __syncthreads();
    #pragma unroll
    for (int k = 0; k < 4; ++k)
        dst[(long long)(n0 + ty + k * 8) * C_ + c0 + tx] =
            __float2bfloat16(t[tx][ty + k * 8]);
}

__global__ void __launch_bounds__(256)
conv_w(const float* w0, const float* w1, const float* w2,
       const float* w3, const float* w4, const float* w5,
       bf16* out, float* D)
{
    const int idx = blockIdx.x * 256 + threadIdx.x;
    if (idx < 2 * B_ * N_) D[idx] = 0.f;
    const int seg = idx >> 16, off = idx & 65535;
    const float* s = (seg == 0) ? w0 : (seg == 1) ? w1 : (seg == 2) ? w2
                   : (seg == 3) ? w3 : (seg == 4) ? w4 : w5;
    out[idx] = __float2bfloat16(s[off]);
}

// ---------------- launch --------------------------------------------------------
extern "C" void kernel_launch(void* const* d_in, const int* in_sizes, int n_in,
                              void* d_out, int out_size)
{
    (void)in_sizes; (void)n_in; (void)out_size;
    const float* x    = (const float*)d_in[0];
    const float* x_h  = (const float*)d_in[1];
    const float* x_v  = (const float*)d_in[2];
    const float* Wa   = (const float*)d_in[3];
    const float* ba   = (const float*)d_in[4];
    const float* ga   = (const float*)d_in[5];
    const float* ta   = (const float*)d_in[6];
    const float* Wv   = (const float*)d_in[7];
    const float* bv   = (const float*)d_in[8];
    const float* gv   = (const float*)d_in[9];
    const float* tv   = (const float*)d_in[10];
    const float* Wgav = (const float*)d_in[11];
    const float* bgav = (const float*)d_in[12];
    const float* Wgah = (const float*)d_in[13];
    const float* bgah = (const float*)d_in[14];
    const float* Wfav = (const float*)d_in[15];
    const float* bfav = (const float*)d_in[16];
    const float* Wfah = (const float*)d_in[17];
    const float* bfah = (const float*)d_in[18];

    bf16 *xT, *fT, *gp, *g2, *Lt, *oT, *Wb;
    float *Dv;
    cudaGetSymbolAddress((void**)&xT, g_xT);
    cudaGetSymbolAddress((void**)&fT, g_fT);
    cudaGetSymbolAddress((void**)&gp, g_gp);
    cudaGetSymbolAddress((void**)&g2, g_g2);
    cudaGetSymbolAddress((void**)&Lt, g_Lt);
    cudaGetSymbolAddress((void**)&oT, g_oT);
    cudaGetSymbolAddress((void**)&Dv, g_D);
    cudaGetSymbolAddress((void**)&Wb, g_Wb);

    cudaFuncSetAttribute(proj_all,    cudaFuncAttributeMaxDynamicSharedMemorySize, SMEM_SZ);
    cudaFuncSetAttribute(mma_logits,  cudaFuncAttributeMaxDynamicSharedMemorySize, SMEM_SZ);
    cudaFuncSetAttribute(mma_apply,   cudaFuncAttributeMaxDynamicSharedMemorySize, SMEM_SZ);
    cudaFuncSetAttribute(outconv_all, cudaFuncAttributeMaxDynamicSharedMemorySize, SMEM_SZ);

    float* out_h = (float*)d_out;
    float* out_v = (float*)d_out + (long long)B_ * C_ * N_;

    dim3 blk(256);
    conv_w<<<1536, blk>>>(Wa, Wv, Wgav, Wgah, Wfav, Wfah, Wb, Dv);
    transpose_k<<<dim3(N_/32, C_/32, 3 * B_), blk>>>(x, x_h, x_v, xT);

    // all 5 projections, one launch
    proj_all<<<dim3(N_/128, 1, 40), blk, SMEM_SZ>>>(xT, Wb, fT, gp,
                                           ba, ga, ta, bv, gv, tv, bgav, bgah);

    // logits + D accumulation, both branches
    const long long segF = (long long)B_ * N_ * MID_;
    mma_logits<<<dim3(N_/128, N_/128, 16), blk, SMEM_SZ>>>(fT, fT + segF,
                                                  fT + 2 * segF, Lt, Dv);

    // fold 1/D into g
    scale_g<<<(int)((2LL * B_ * MID_ * N_ / 2) / 256), blk>>>(gp, Dv, g2);

    // apply, both branches
    mma_apply<<<dim3(1, N_/128, 16), blk, SMEM_SZ>>>(Lt, g2, oT);

    // output convs + residual, both branches
    outconv_all<<<dim3(N_/128, C_/128, 16), blk, SMEM_SZ>>>(Wb, oT, x, bfav, bfah,
                                                   out_v, out_h);
}